// round 8
// baseline (speedup 1.0000x reference)
#include <cuda_runtime.h>
#include <cuda_bf16.h>
#include <math.h>
#include <stdint.h>

#define BB   512
#define TT   128
#define DIN  256
#define HH   1024
#define G4   4096          // 4*HH
#define MTOT (TT*BB)       // 65536
#define NCH  16            // K chunks per step (1024/64)
#define CK   64            // k per chunk (64 bf16 = 128B rows)
#define NBLK 256           // persistent grid size (co-resident: 2/SM x 148)

// ---------------- scratch (device globals: no allocations allowed) ----------
__device__ float g_X [(size_t)TT * BB * G4];   // gate pre-activations (cols n=j*4+g)
__device__ float g_H1[(size_t)TT * BB * HH];   // layer-1 fp32 hidden history
__device__ float g_H2[(size_t)TT * BB * HH];   // layer-2 fp32 hidden history
__device__ float g_c [BB * HH];                // cell state (reused per layer)

__device__ float g_Wr1[(size_t)DIN * G4];      // W1 cols reordered n=j*4+g
__device__ float g_Wr2[(size_t)HH  * G4];
__device__ float g_br1[G4];
__device__ float g_br2[G4];

// U transposed+gate-interleaved+bf16-split: [layer][n=j*4+g][k]
__device__ __nv_bfloat16 g_Uhi[2][(size_t)G4 * HH];
__device__ __nv_bfloat16 g_Ulo[2][(size_t)G4 * HH];
// h ping-pong, bf16 hi/lo split: [parity][m*HH + j]
__device__ __nv_bfloat16 g_hhi[2][(size_t)BB * HH];
__device__ __nv_bfloat16 g_hlo[2][(size_t)BB * HH];

// software grid barrier state
__device__ unsigned g_bar_cnt;
__device__ unsigned g_bar_gen;

// ---------------- helpers ----------------------------------------------------
__device__ __forceinline__ uint32_t smem_to_u32(const void* p) {
    uint32_t a;
    asm("{ .reg .u64 t; cvta.to.shared.u64 t, %1; cvt.u32.u64 %0, t; }"
        : "=r"(a) : "l"(p));
    return a;
}
#define SMEM_SWIZZLE_128B(b) ((b) ^ (((b) >> 3) & 0x70))

__device__ __forceinline__ void cp16(uint32_t dst, const void* src) {
    asm volatile("cp.async.cg.shared.global [%0], [%1], 16;" :: "r"(dst), "l"(src));
}
#define CP_COMMIT() asm volatile("cp.async.commit_group;" ::: "memory")
#define CP_WAIT(n)  asm volatile("cp.async.wait_group %0;" :: "n"(n) : "memory")

__device__ __forceinline__ void ldsm4(uint32_t* r, uint32_t addr) {
    asm volatile("ldmatrix.sync.aligned.m8n8.x4.shared.b16 {%0,%1,%2,%3}, [%4];"
        : "=r"(r[0]), "=r"(r[1]), "=r"(r[2]), "=r"(r[3]) : "r"(addr));
}
__device__ __forceinline__ void mma16816(float* d, const uint32_t* a, const uint32_t* b) {
    asm volatile("mma.sync.aligned.m16n8k16.row.col.f32.bf16.bf16.f32 "
        "{%0,%1,%2,%3}, {%4,%5,%6,%7}, {%8,%9}, {%0,%1,%2,%3};"
        : "+f"(d[0]), "+f"(d[1]), "+f"(d[2]), "+f"(d[3])
        : "r"(a[0]), "r"(a[1]), "r"(a[2]), "r"(a[3]), "r"(b[0]), "r"(b[1]));
}

__device__ __forceinline__ float sigmoidf_(float x) { return 1.f / (1.f + expf(-x)); }

// all threads: stores done -> __threadfence -> __syncthreads -> call this
__device__ __forceinline__ void grid_barrier(unsigned expect) {
    if (threadIdx.x == 0) {
        unsigned prev = atomicAdd(&g_bar_cnt, 1u);
        if (prev == NBLK - 1) {
            atomicExch(&g_bar_cnt, 0u);
            __threadfence();
            atomicAdd(&g_bar_gen, 1u);
        } else {
            for (;;) {
                unsigned g;
                asm volatile("ld.acquire.gpu.u32 %0, [%1];" : "=r"(g) : "l"(&g_bar_gen));
                if (g >= expect) break;
                __nanosleep(64);
            }
        }
    }
    __syncthreads();
}

// ---------------- fp32x2 packed-FMA helpers (input GEMM path) ----------------
__device__ __forceinline__ unsigned long long dup2(float a) {
    unsigned long long r;
    asm("mov.b64 %0, {%1, %1};" : "=l"(r) : "r"(__float_as_uint(a)));
    return r;
}
__device__ __forceinline__ void ffma2(unsigned long long& d, unsigned long long a,
                                      unsigned long long b) {
    asm("fma.rn.f32x2 %0, %1, %2, %0;" : "+l"(d) : "l"(a), "l"(b));
}
__device__ __forceinline__ float lo2(unsigned long long v) { return __uint_as_float((unsigned)v); }
__device__ __forceinline__ float hi2(unsigned long long v) { return __uint_as_float((unsigned)(v >> 32)); }

// ============================================================================
// Prep kernels
// ============================================================================
__global__ void reorder_W_kernel(const float* __restrict__ W,
                                 const float* __restrict__ b,
                                 int KD, int sel)
{
    float* Wr = sel ? g_Wr2 : g_Wr1;
    float* br = sel ? g_br2 : g_br1;
    int i = blockIdx.x * blockDim.x + threadIdx.x;
    if (i < KD * G4) {
        int k = i >> 12, n = i & 4095;
        int j = n >> 2, g = n & 3;
        Wr[i] = W[(size_t)k * G4 + g * HH + j];
    }
    if (i < G4) {
        int j = i >> 2, g = i & 3;
        br[i] = b[g * HH + j];
    }
}

__global__ void split_U_kernel(const float* __restrict__ U, int layer)
{
    int i = blockIdx.x * blockDim.x + threadIdx.x;   // i = n*HH + k
    if (i >= G4 * HH) return;
    int n = i >> 10, k = i & 1023;
    int j = n >> 2, g = n & 3;
    float v = U[(size_t)k * G4 + g * HH + j];
    __nv_bfloat16 hi = __float2bfloat16(v);
    __nv_bfloat16 lo = __float2bfloat16(v - __bfloat162float(hi));
    g_Uhi[layer][i] = hi;
    g_Ulo[layer][i] = lo;
}

__global__ void zero_state_kernel()
{
    int i = blockIdx.x * blockDim.x + threadIdx.x;
    if (i < BB * HH) {
        g_c[i] = 0.f;
        g_hhi[0][i] = __float2bfloat16(0.f);
        g_hlo[0][i] = __float2bfloat16(0.f);
    }
    if (i == 0) { g_bar_cnt = 0u; g_bar_gen = 0u; }
}

// ============================================================================
// Input-path GEMM (FFMA2, proven): g_X[m][n] = A[m][:] @ Wr[:, n] + br[n]
// ============================================================================
template<int KD, bool CHARS>
__global__ __launch_bounds__(256, 2)
void gemm_bias_kernel(const float* __restrict__ A)
{
    const float* __restrict__ W    = CHARS ? g_Wr1 : g_Wr2;
    const float* __restrict__ bias = CHARS ? g_br1 : g_br2;

    __shared__ __align__(16) float As[16][132];
    __shared__ __align__(16) float Bs[16][128];

    const int tid = threadIdx.x;
    const int tx  = tid & 15;
    const int ty  = tid >> 4;
    const int n0  = blockIdx.x * 128;
    const int m0  = blockIdx.y * 128;

    const float* Abase = CHARS ? A : g_H1;

    unsigned long long acc[8][4];
    #pragma unroll
    for (int i = 0; i < 8; i++)
        #pragma unroll
        for (int p = 0; p < 4; p++) acc[i][p] = 0ull;

    const int a_k = tid & 15;
    const int a_m = tid >> 4;
    const int b_c = tid & 127;
    const int b_k = tid >> 7;

    for (int kt = 0; kt < KD; kt += 16) {
        #pragma unroll
        for (int r = 0; r < 8; r++) {
            int m = m0 + a_m + 16 * r;
            size_t row = CHARS ? ((size_t)(m & 511) * TT + (m >> 9)) * KD
                               : (size_t)m * KD;
            As[a_k][a_m + 16 * r] = Abase[row + kt + a_k];
        }
        #pragma unroll
        for (int r = 0; r < 8; r++) {
            int k = b_k + 2 * r;
            Bs[k][b_c] = W[(size_t)(kt + k) * G4 + n0 + b_c];
        }
        __syncthreads();

        #pragma unroll
        for (int k = 0; k < 16; k++) {
            float4 a0 = *(const float4*)&As[k][ty * 4];
            float4 a1 = *(const float4*)&As[k][64 + ty * 4];
            unsigned long long bp[4];
            bp[0] = *(const unsigned long long*)&Bs[k][tx * 4];
            bp[1] = *(const unsigned long long*)&Bs[k][tx * 4 + 2];
            bp[2] = *(const unsigned long long*)&Bs[k][64 + tx * 4];
            bp[3] = *(const unsigned long long*)&Bs[k][64 + tx * 4 + 2];
            float av[8] = {a0.x, a0.y, a0.z, a0.w, a1.x, a1.y, a1.z, a1.w};
            #pragma unroll
            for (int i = 0; i < 8; i++) {
                unsigned long long ad = dup2(av[i]);
                #pragma unroll
                for (int p = 0; p < 4; p++) ffma2(acc[i][p], ad, bp[p]);
            }
        }
        __syncthreads();
    }

    #pragma unroll
    for (int i = 0; i < 8; i++) {
        int m = m0 + ((i < 4) ? (ty * 4 + i) : (64 + ty * 4 + i - 4));
        #pragma unroll
        for (int q = 0; q < 2; q++) {
            int n = n0 + q * 64 + tx * 4;
            float4 v;
            v.x = lo2(acc[i][q * 2])     + bias[n + 0];
            v.y = hi2(acc[i][q * 2])     + bias[n + 1];
            v.z = lo2(acc[i][q * 2 + 1]) + bias[n + 2];
            v.w = hi2(acc[i][q * 2 + 1]) + bias[n + 3];
            *(float4*)&g_X[(size_t)m * G4 + n] = v;
        }
    }
}

// ============================================================================
// Persistent recurrent layer kernel: 128 fused timesteps, software grid barrier.
// Block: M=64(batch) x N=128(=32j x 4gates), K=1024, 3-term bf16 mma.sync.
// SMEM (96KB): A[buf][hi/lo] 4x8KB @0; B[buf][hi/lo] 4x16KB @32KB.
// Epilogue z-staging uses only the A region (two 32-row phases) so B buf0
// can be prefetched (U is time-invariant) before the grid barrier.
// ============================================================================
#define SM_STEP_TOTAL 98304

__device__ __forceinline__ void issue_A(uint32_t sb, int buf, int kt,
    const __nv_bfloat16* hhi, const __nv_bfloat16* hlo, int m0, int tid)
{
    uint32_t aHi = sb + buf * 16384;
    uint32_t aLo = aHi + 8192;
    #pragma unroll
    for (int i = 0; i < 2; i++) {                 // A: 64 rows x 8 segs
        int idx = tid + 256 * i;
        int row = idx >> 3, cs = idx & 7;
        uint32_t off = SMEM_SWIZZLE_128B((uint32_t)(row * 128 + cs * 16));
        size_t src = (size_t)(m0 + row) * HH + kt + cs * 8;
        cp16(aHi + off, hhi + src);
        cp16(aLo + off, hlo + src);
    }
}

__device__ __forceinline__ void issue_B(uint32_t sb, int buf, int kt,
    const __nv_bfloat16* Uhi, const __nv_bfloat16* Ulo, int nrow0, int tid)
{
    uint32_t bHi = sb + 32768 + buf * 32768;
    uint32_t bLo = bHi + 16384;
    #pragma unroll
    for (int i = 0; i < 4; i++) {                 // B: 128 rows x 8 segs
        int idx = tid + 256 * i;
        int row = idx >> 3, cs = idx & 7;
        uint32_t off = SMEM_SWIZZLE_128B((uint32_t)(row * 128 + cs * 16));
        size_t src = (size_t)(nrow0 + row) * HH + kt + cs * 8;
        cp16(bHi + off, Uhi + src);
        cp16(bLo + off, Ulo + src);
    }
}

__global__ __launch_bounds__(256, 2)
void lstm_layer_persistent(int layer)
{
    extern __shared__ __align__(128) char smem[];
    const uint32_t sb = smem_to_u32(smem);
    const int tid  = threadIdx.x;
    const int wid  = tid >> 5;
    const int lane = tid & 31;
    const int bidx = blockIdx.y * gridDim.x + blockIdx.x;   // launched 1-D anyway
    (void)bidx;
    const int nrow0 = blockIdx.x * 128;   // n-rows of U for this block
    const int m0    = blockIdx.y * 64;
    const int j0    = blockIdx.x * 32;

    const __nv_bfloat16* Uhi = g_Uhi[layer];
    const __nv_bfloat16* Ulo = g_Ulo[layer];
    float* Hist = layer ? g_H2 : g_H1;

    const int m_warp = (wid & 1) * 32;    // 2 m-tiles of 32
    const int n_warp = (wid >> 1) * 32;   // 4 n-tiles of 32
    const int rsel = lane & 15;
    const int csel = (lane >> 4) * 16;

    float* zs32 = (float*)smem;           // [32][132] staging, inside A region

    // prologue: chunk 0 of step 0
    issue_B(sb, 0, 0, Uhi, Ulo, nrow0, tid);
    issue_A(sb, 0, 0, g_hhi[0], g_hlo[0], m0, tid);
    CP_COMMIT();

    for (int t = 0; t < TT; t++) {
        const int par = t & 1;
        const __nv_bfloat16* hhi = g_hhi[par];
        const __nv_bfloat16* hlo = g_hlo[par];

        float acc[2][4][4];
        #pragma unroll
        for (int mf = 0; mf < 2; mf++)
            #pragma unroll
            for (int nf = 0; nf < 4; nf++)
                #pragma unroll
                for (int d = 0; d < 4; d++) acc[mf][nf][d] = 0.f;

        int buf = 0;
        for (int c = 0; c < NCH; c++) {
            if (c + 1 < NCH) {
                issue_A(sb, buf ^ 1, (c + 1) * CK, hhi, hlo, m0, tid);
                issue_B(sb, buf ^ 1, (c + 1) * CK, Uhi, Ulo, nrow0, tid);
                CP_COMMIT();
                CP_WAIT(1);
            } else {
                CP_WAIT(0);
            }
            __syncthreads();

            const uint32_t sAh = sb + buf * 16384;
            const uint32_t sAl = sAh + 8192;
            const uint32_t sBh = sb + 32768 + buf * 32768;
            const uint32_t sBl = sBh + 16384;

            #pragma unroll
            for (int s = 0; s < 4; s++) {
                uint32_t aH[2][4], aL[2][4], bH[4][2], bL[4][2];
                #pragma unroll
                for (int mf = 0; mf < 2; mf++) {
                    uint32_t off = SMEM_SWIZZLE_128B(
                        (uint32_t)((m_warp + mf * 16 + rsel) * 128 + s * 32 + csel));
                    ldsm4(aH[mf], sAh + off);
                    ldsm4(aL[mf], sAl + off);
                }
                #pragma unroll
                for (int nb = 0; nb < 2; nb++) {
                    uint32_t off = SMEM_SWIZZLE_128B(
                        (uint32_t)((n_warp + nb * 16 + rsel) * 128 + s * 32 + csel));
                    uint32_t r[4];
                    ldsm4(r, sBh + off);
                    bH[nb * 2][0] = r[0]; bH[nb * 2][1] = r[2];
                    bH[nb * 2 + 1][0] = r[1]; bH[nb * 2 + 1][1] = r[3];
                    ldsm4(r, sBl + off);
                    bL[nb * 2][0] = r[0]; bL[nb * 2][1] = r[2];
                    bL[nb * 2 + 1][0] = r[1]; bL[nb * 2 + 1][1] = r[3];
                }
                #pragma unroll
                for (int mf = 0; mf < 2; mf++)
                    #pragma unroll
                    for (int nf = 0; nf < 4; nf++) {
                        mma16816(acc[mf][nf], aH[mf], bH[nf]);
                        mma16816(acc[mf][nf], aH[mf], bL[nf]);
                        mma16816(acc[mf][nf], aL[mf], bH[nf]);
                    }
            }
            __syncthreads();
            buf ^= 1;
        }

        // ---- epilogue in two 32-row phases (stays inside A smem region) ----
        __nv_bfloat16* nhhi = g_hhi[par ^ 1];
        __nv_bfloat16* nhlo = g_hlo[par ^ 1];

        #pragma unroll
        for (int p = 0; p < 2; p++) {
            if ((wid & 1) == p) {
                #pragma unroll
                for (int mf = 0; mf < 2; mf++)
                    #pragma unroll
                    for (int nf = 0; nf < 4; nf++)
                        #pragma unroll
                        for (int d = 0; d < 4; d++) {
                            int mrow = mf * 16 + (lane >> 2) + (d >> 1) * 8;  // 0..31
                            int n = n_warp + nf * 8 + (lane & 3) * 2 + (d & 1);
                            zs32[mrow * 132 + n] = acc[mf][nf][d];
                        }
            }
            __syncthreads();
            #pragma unroll
            for (int r = 0; r < 4; r++) {
                int e  = tid + 256 * r;          // < 1024
                int ml = e >> 5;
                int jl = e & 31;
                int mg = m0 + p * 32 + ml;
                int j  = j0 + jl;
                float4 z = *(const float4*)&zs32[ml * 132 + jl * 4];
                const float* Xrow = g_X + ((size_t)t * BB + mg) * G4 + blockIdx.x * 128;
                float4 xz = *(const float4*)(Xrow + jl * 4);
                float zi = z.x + xz.x;
                float zf = z.y + xz.y;
                float zg = z.z + xz.z;
                float zo = z.w + xz.w;
                float ig = sigmoidf_(zi);
                float fg = sigmoidf_(zf);
                float gg = tanhf(zg);
                float og = sigmoidf_(zo);
                size_t cidx = (size_t)mg * HH + j;
                float cc = fg * g_c[cidx] + ig * gg;
                g_c[cidx] = cc;
                float h = og * tanhf(cc);
                Hist[((size_t)t * BB + mg) * HH + j] = h;
                __nv_bfloat16 hh = __float2bfloat16(h);
                nhhi[cidx] = hh;
                nhlo[cidx] = __float2bfloat16(h - __bfloat162float(hh));
            }
            __syncthreads();
        }

        if (t + 1 < TT) {
            __threadfence();
            __syncthreads();
            // U is time-invariant: prefetch next step's B chunk0 before barrier
            issue_B(sb, 0, 0, Uhi, Ulo, nrow0, tid);
            grid_barrier((unsigned)(t + 1));
            // new h is now globally visible: fetch A chunk0
            issue_A(sb, 0, 0, g_hhi[(t + 1) & 1], g_hlo[(t + 1) & 1], m0, tid);
            CP_COMMIT();
        }
    }
}

// ---------------- output head ------------------------------------------------
__global__ void dense_out_kernel(const int* __restrict__ seq,
                                 const float* __restrict__ Wd,
                                 const float* __restrict__ bd,
                                 float* __restrict__ out)
{
    int b   = blockIdx.x;
    int tid = threadIdx.x;   // 128 threads
    const float* hrow = g_H2 + ((size_t)(seq[b] - 1) * BB + b) * HH;
    float s0 = 0.f, s1 = 0.f, s2 = 0.f;
    for (int j = tid; j < HH; j += 128) {
        float h = hrow[j];
        s0 += h * Wd[j * 3 + 0];
        s1 += h * Wd[j * 3 + 1];
        s2 += h * Wd[j * 3 + 2];
    }
    __shared__ float sm[3][128];
    sm[0][tid] = s0; sm[1][tid] = s1; sm[2][tid] = s2;
    __syncthreads();
    for (int s = 64; s > 0; s >>= 1) {
        if (tid < s) {
            sm[0][tid] += sm[0][tid + s];
            sm[1][tid] += sm[1][tid + s];
            sm[2][tid] += sm[2][tid + s];
        }
        __syncthreads();
    }
    if (tid == 0) {
        out[b * 3 + 0] = fmaxf(sm[0][0] + bd[0], 0.f);
        out[b * 3 + 1] = fmaxf(sm[1][0] + bd[1], 0.f);
        out[b * 3 + 2] = fmaxf(sm[2][0] + bd[2], 0.f);
    }
}

// ---------------- launch -----------------------------------------------------
extern "C" void kernel_launch(void* const* d_in, const int* in_sizes, int n_in,
                              void* d_out, int out_size)
{
    const float* chars = (const float*)d_in[0];
    const int*   seq   = (const int*)  d_in[1];
    const float* W1    = (const float*)d_in[2];
    const float* U1    = (const float*)d_in[3];
    const float* b1    = (const float*)d_in[4];
    const float* W2    = (const float*)d_in[5];
    const float* U2    = (const float*)d_in[6];
    const float* b2    = (const float*)d_in[7];
    const float* Wd    = (const float*)d_in[8];
    const float* bd    = (const float*)d_in[9];
    float*       out   = (float*)d_out;

    cudaFuncSetAttribute(lstm_layer_persistent,
                         cudaFuncAttributeMaxDynamicSharedMemorySize, SM_STEP_TOTAL);

    dim3 blk(256);
    dim3 gX(G4 / 128, MTOT / 128);   // 32 x 512
    dim3 gS(G4 / 128, BB / 64);      // 32 x 8 = 256 persistent blocks

    // --- prep ---
    reorder_W_kernel<<<(DIN * G4 + 255) / 256, 256>>>(W1, b1, DIN, 0);
    reorder_W_kernel<<<(HH  * G4 + 255) / 256, 256>>>(W2, b2, HH,  1);
    split_U_kernel<<<(G4 * HH + 255) / 256, 256>>>(U1, 0);
    split_U_kernel<<<(G4 * HH + 255) / 256, 256>>>(U2, 1);

    // --- layer 1 ---
    gemm_bias_kernel<DIN, true><<<gX, blk>>>(chars);
    zero_state_kernel<<<(BB * HH + 255) / 256, 256>>>();
    lstm_layer_persistent<<<gS, blk, SM_STEP_TOTAL>>>(0);

    // --- layer 2 ---
    gemm_bias_kernel<HH, false><<<gX, blk>>>(nullptr);
    zero_state_kernel<<<(BB * HH + 255) / 256, 256>>>();
    lstm_layer_persistent<<<gS, blk, SM_STEP_TOTAL>>>(1);

    // --- gather + dense + relu ---
    dense_out_kernel<<<BB, 128>>>(seq, Wd, bd, out);
}

// round 9
// speedup vs baseline: 1.1696x; 1.1696x over previous
#include <cuda_runtime.h>
#include <cuda_bf16.h>
#include <cuda_fp16.h>
#include <math.h>
#include <stdint.h>

#define BB   512
#define TT   128
#define DIN  256
#define HH   1024
#define G4   4096          // 4*HH
#define MTOT (TT*BB)       // 65536
#define NCH  16            // K chunks per step (1024/64)
#define CK   64            // k per chunk (64 fp16 = 128B rows)

// ---------------- scratch (device globals: no allocations allowed) ----------
__device__ float g_X [(size_t)TT * BB * G4];   // gate pre-activations (cols n=j*4+g)
__device__ float g_H1[(size_t)TT * BB * HH];   // layer-1 fp32 hidden history
__device__ float g_H2[(size_t)TT * BB * HH];   // layer-2 fp32 hidden history
__device__ float g_c [BB * HH];                // cell state (reused per layer)

__device__ float g_Wr1[(size_t)DIN * G4];      // W1 cols reordered n=j*4+g
__device__ float g_Wr2[(size_t)HH  * G4];
__device__ float g_br1[G4];
__device__ float g_br2[G4];

// U transposed+gate-interleaved+fp16-split: [layer][n=j*4+g][k]
__device__ __half g_Uhi[2][(size_t)G4 * HH];
__device__ __half g_Ulo[2][(size_t)G4 * HH];
// h ping-pong, single fp16: [parity][m*HH + j]
__device__ __half g_h16[2][(size_t)BB * HH];

// ---------------- helpers ----------------------------------------------------
__device__ __forceinline__ uint32_t smem_to_u32(const void* p) {
    uint32_t a;
    asm("{ .reg .u64 t; cvta.to.shared.u64 t, %1; cvt.u32.u64 %0, t; }"
        : "=r"(a) : "l"(p));
    return a;
}
#define SMEM_SWIZZLE_128B(b) ((b) ^ (((b) >> 3) & 0x70))

__device__ __forceinline__ void cp16(uint32_t dst, const void* src) {
    asm volatile("cp.async.cg.shared.global [%0], [%1], 16;" :: "r"(dst), "l"(src));
}
#define CP_COMMIT() asm volatile("cp.async.commit_group;" ::: "memory")
#define CP_WAIT(n)  asm volatile("cp.async.wait_group %0;" :: "n"(n) : "memory")

__device__ __forceinline__ void ldsm4(uint32_t* r, uint32_t addr) {
    asm volatile("ldmatrix.sync.aligned.m8n8.x4.shared.b16 {%0,%1,%2,%3}, [%4];"
        : "=r"(r[0]), "=r"(r[1]), "=r"(r[2]), "=r"(r[3]) : "r"(addr));
}
__device__ __forceinline__ void mma16816h(float* d, const uint32_t* a, const uint32_t* b) {
    asm volatile("mma.sync.aligned.m16n8k16.row.col.f32.f16.f16.f32 "
        "{%0,%1,%2,%3}, {%4,%5,%6,%7}, {%8,%9}, {%0,%1,%2,%3};"
        : "+f"(d[0]), "+f"(d[1]), "+f"(d[2]), "+f"(d[3])
        : "r"(a[0]), "r"(a[1]), "r"(a[2]), "r"(a[3]), "r"(b[0]), "r"(b[1]));
}

__device__ __forceinline__ float sigmoidf_(float x) { return 1.f / (1.f + expf(-x)); }

// ---------------- fp32x2 packed-FMA helpers (input GEMM path) ----------------
__device__ __forceinline__ unsigned long long dup2(float a) {
    unsigned long long r;
    asm("mov.b64 %0, {%1, %1};" : "=l"(r) : "r"(__float_as_uint(a)));
    return r;
}
__device__ __forceinline__ void ffma2(unsigned long long& d, unsigned long long a,
                                      unsigned long long b) {
    asm("fma.rn.f32x2 %0, %1, %2, %0;" : "+l"(d) : "l"(a), "l"(b));
}
__device__ __forceinline__ float lo2(unsigned long long v) { return __uint_as_float((unsigned)v); }
__device__ __forceinline__ float hi2(unsigned long long v) { return __uint_as_float((unsigned)(v >> 32)); }

// ============================================================================
// Prep kernels
// ============================================================================
__global__ void reorder_W_kernel(const float* __restrict__ W,
                                 const float* __restrict__ b,
                                 int KD, int sel)
{
    float* Wr = sel ? g_Wr2 : g_Wr1;
    float* br = sel ? g_br2 : g_br1;
    int i = blockIdx.x * blockDim.x + threadIdx.x;
    if (i < KD * G4) {
        int k = i >> 12, n = i & 4095;
        int j = n >> 2, g = n & 3;
        Wr[i] = W[(size_t)k * G4 + g * HH + j];
    }
    if (i < G4) {
        int j = i >> 2, g = i & 3;
        br[i] = b[g * HH + j];
    }
}

// Transpose + gate-interleave + fp16-split U: out[n=j*4+g][k] from U[k][g*HH+j]
__global__ void split_U_kernel(const float* __restrict__ U, int layer)
{
    int i = blockIdx.x * blockDim.x + threadIdx.x;   // i = n*HH + k
    if (i >= G4 * HH) return;
    int n = i >> 10, k = i & 1023;
    int j = n >> 2, g = n & 3;
    float v = U[(size_t)k * G4 + g * HH + j];
    __half hi = __float2half(v);
    __half lo = __float2half(v - __half2float(hi));
    g_Uhi[layer][i] = hi;
    g_Ulo[layer][i] = lo;
}

__global__ void zero_state_kernel()
{
    int i = blockIdx.x * blockDim.x + threadIdx.x;
    if (i < BB * HH) {
        g_c[i] = 0.f;
        g_h16[0][i] = __float2half(0.f);
    }
}

// ============================================================================
// Input-path GEMM (FFMA2, proven): g_X[m][n] = A[m][:] @ Wr[:, n] + br[n]
// ============================================================================
template<int KD, bool CHARS>
__global__ __launch_bounds__(256, 2)
void gemm_bias_kernel(const float* __restrict__ A)
{
    const float* __restrict__ W    = CHARS ? g_Wr1 : g_Wr2;
    const float* __restrict__ bias = CHARS ? g_br1 : g_br2;

    __shared__ __align__(16) float As[16][132];
    __shared__ __align__(16) float Bs[16][128];

    const int tid = threadIdx.x;
    const int tx  = tid & 15;
    const int ty  = tid >> 4;
    const int n0  = blockIdx.x * 128;
    const int m0  = blockIdx.y * 128;

    const float* Abase = CHARS ? A : g_H1;

    unsigned long long acc[8][4];
    #pragma unroll
    for (int i = 0; i < 8; i++)
        #pragma unroll
        for (int p = 0; p < 4; p++) acc[i][p] = 0ull;

    const int a_k = tid & 15;
    const int a_m = tid >> 4;
    const int b_c = tid & 127;
    const int b_k = tid >> 7;

    for (int kt = 0; kt < KD; kt += 16) {
        #pragma unroll
        for (int r = 0; r < 8; r++) {
            int m = m0 + a_m + 16 * r;
            size_t row = CHARS ? ((size_t)(m & 511) * TT + (m >> 9)) * KD
                               : (size_t)m * KD;
            As[a_k][a_m + 16 * r] = Abase[row + kt + a_k];
        }
        #pragma unroll
        for (int r = 0; r < 8; r++) {
            int k = b_k + 2 * r;
            Bs[k][b_c] = W[(size_t)(kt + k) * G4 + n0 + b_c];
        }
        __syncthreads();

        #pragma unroll
        for (int k = 0; k < 16; k++) {
            float4 a0 = *(const float4*)&As[k][ty * 4];
            float4 a1 = *(const float4*)&As[k][64 + ty * 4];
            unsigned long long bp[4];
            bp[0] = *(const unsigned long long*)&Bs[k][tx * 4];
            bp[1] = *(const unsigned long long*)&Bs[k][tx * 4 + 2];
            bp[2] = *(const unsigned long long*)&Bs[k][64 + tx * 4];
            bp[3] = *(const unsigned long long*)&Bs[k][64 + tx * 4 + 2];
            float av[8] = {a0.x, a0.y, a0.z, a0.w, a1.x, a1.y, a1.z, a1.w};
            #pragma unroll
            for (int i = 0; i < 8; i++) {
                unsigned long long ad = dup2(av[i]);
                #pragma unroll
                for (int p = 0; p < 4; p++) ffma2(acc[i][p], ad, bp[p]);
            }
        }
        __syncthreads();
    }

    #pragma unroll
    for (int i = 0; i < 8; i++) {
        int m = m0 + ((i < 4) ? (ty * 4 + i) : (64 + ty * 4 + i - 4));
        #pragma unroll
        for (int q = 0; q < 2; q++) {
            int n = n0 + q * 64 + tx * 4;
            float4 v;
            v.x = lo2(acc[i][q * 2])     + bias[n + 0];
            v.y = hi2(acc[i][q * 2])     + bias[n + 1];
            v.z = lo2(acc[i][q * 2 + 1]) + bias[n + 2];
            v.w = hi2(acc[i][q * 2 + 1]) + bias[n + 3];
            *(float4*)&g_X[(size_t)m * G4 + n] = v;
        }
    }
}

// ============================================================================
// Recurrent step: fp16 2-term mma.sync (z = h16@Uhi + h16@Ulo, fp32 acc).
// Block: M=64(batch) x N=128(=32j x 4gates), K=1024. grid (32,8)=256 blocks.
// 8 warps, warp tile 32x32. cp.async double-buffered SW128 smem tiles.
// SMEM (80KB): A[2 bufs] 2x8KB @0; B[buf][hi/lo] 4x16KB @16KB.
// ============================================================================
#define SM_STEP_TOTAL 81920

__device__ __forceinline__ void issue_chunk(
    uint32_t sb, int buf, int kt,
    const __half* h16, const __half* Uhi, const __half* Ulo,
    int m0, int nrow0, int tid)
{
    uint32_t aA  = sb + buf * 8192;
    uint32_t bHi = sb + 16384 + buf * 32768;
    uint32_t bLo = bHi + 16384;
    #pragma unroll
    for (int i = 0; i < 2; i++) {                 // A: 64 rows x 8 segs
        int idx = tid + 256 * i;
        int row = idx >> 3, cs = idx & 7;
        uint32_t off = SMEM_SWIZZLE_128B((uint32_t)(row * 128 + cs * 16));
        size_t src = (size_t)(m0 + row) * HH + kt + cs * 8;
        cp16(aA + off, h16 + src);
    }
    #pragma unroll
    for (int i = 0; i < 4; i++) {                 // B: 128 rows x 8 segs (hi+lo)
        int idx = tid + 256 * i;
        int row = idx >> 3, cs = idx & 7;
        uint32_t off = SMEM_SWIZZLE_128B((uint32_t)(row * 128 + cs * 16));
        size_t src = (size_t)(nrow0 + row) * HH + kt + cs * 8;
        cp16(bHi + off, Uhi + src);
        cp16(bLo + off, Ulo + src);
    }
    CP_COMMIT();
}

__global__ __launch_bounds__(256, 2)
void lstm_step_mma(int t, int layer)
{
    extern __shared__ __align__(128) char smem[];
    const uint32_t sb = smem_to_u32(smem);
    const int tid  = threadIdx.x;
    const int wid  = tid >> 5;
    const int lane = tid & 31;
    const int nrow0 = blockIdx.x * 128;   // n-rows of U for this block
    const int m0    = blockIdx.y * 64;
    const int par   = t & 1;

    const __half* h16 = g_h16[par];
    const __half* Uhi = g_Uhi[layer];
    const __half* Ulo = g_Ulo[layer];

    const int m_warp = (wid & 1) * 32;    // 2 m-tiles of 32
    const int n_warp = (wid >> 1) * 32;   // 4 n-tiles of 32

    float acc[2][4][4];
    #pragma unroll
    for (int mf = 0; mf < 2; mf++)
        #pragma unroll
        for (int nf = 0; nf < 4; nf++)
            #pragma unroll
            for (int d = 0; d < 4; d++) acc[mf][nf][d] = 0.f;

    const int rsel = lane & 15;
    const int csel = (lane >> 4) * 16;

    issue_chunk(sb, 0, 0, h16, Uhi, Ulo, m0, nrow0, tid);

    int buf = 0;
    for (int c = 0; c < NCH; c++) {
        if (c + 1 < NCH) {
            issue_chunk(sb, buf ^ 1, (c + 1) * CK, h16, Uhi, Ulo, m0, nrow0, tid);
            CP_WAIT(1);
        } else {
            CP_WAIT(0);
        }
        __syncthreads();

        const uint32_t sA  = sb + buf * 8192;
        const uint32_t sBh = sb + 16384 + buf * 32768;
        const uint32_t sBl = sBh + 16384;

        #pragma unroll
        for (int s = 0; s < 4; s++) {
            uint32_t aF[2][4], bH[4][2], bL[4][2];
            #pragma unroll
            for (int mf = 0; mf < 2; mf++) {
                uint32_t off = SMEM_SWIZZLE_128B(
                    (uint32_t)((m_warp + mf * 16 + rsel) * 128 + s * 32 + csel));
                ldsm4(aF[mf], sA + off);
            }
            #pragma unroll
            for (int nb = 0; nb < 2; nb++) {
                uint32_t off = SMEM_SWIZZLE_128B(
                    (uint32_t)((n_warp + nb * 16 + rsel) * 128 + s * 32 + csel));
                uint32_t r[4];
                ldsm4(r, sBh + off);
                bH[nb * 2][0] = r[0]; bH[nb * 2][1] = r[2];
                bH[nb * 2 + 1][0] = r[1]; bH[nb * 2 + 1][1] = r[3];
                ldsm4(r, sBl + off);
                bL[nb * 2][0] = r[0]; bL[nb * 2][1] = r[2];
                bL[nb * 2 + 1][0] = r[1]; bL[nb * 2 + 1][1] = r[3];
            }
            #pragma unroll
            for (int mf = 0; mf < 2; mf++)
                #pragma unroll
                for (int nf = 0; nf < 4; nf++) {
                    mma16816h(acc[mf][nf], aF[mf], bH[nf]);
                    mma16816h(acc[mf][nf], aF[mf], bL[nf]);
                }
        }
        __syncthreads();
        buf ^= 1;
    }

    // ---- epilogue: stage z via smem so each thread gets 4 gates of one j ----
    float* zs = (float*)smem;               // [64][132] fp32 (reuses tiles)
    #pragma unroll
    for (int mf = 0; mf < 2; mf++)
        #pragma unroll
        for (int nf = 0; nf < 4; nf++)
            #pragma unroll
            for (int d = 0; d < 4; d++) {
                int m = m_warp + mf * 16 + (lane >> 2) + (d >> 1) * 8;
                int n = n_warp + nf * 8 + (lane & 3) * 2 + (d & 1);
                zs[m * 132 + n] = acc[mf][nf][d];
            }
    __syncthreads();

    float* Hist = layer ? g_H2 : g_H1;
    __half* nh16 = g_h16[par ^ 1];
    const int j0 = blockIdx.x * 32;

    #pragma unroll
    for (int r = 0; r < 8; r++) {
        int e  = tid + 256 * r;
        int m  = e >> 5;
        int jl = e & 31;
        int mg = m0 + m;
        int j  = j0 + jl;
        float4 z = *(const float4*)&zs[m * 132 + jl * 4];
        const float* Xrow = g_X + ((size_t)t * BB + mg) * G4 + blockIdx.x * 128;
        float4 xz = *(const float4*)(Xrow + jl * 4);
        float zi = z.x + xz.x;
        float zf = z.y + xz.y;
        float zg = z.z + xz.z;
        float zo = z.w + xz.w;
        float ig = sigmoidf_(zi);
        float fg = sigmoidf_(zf);
        float gg = tanhf(zg);
        float og = sigmoidf_(zo);
        size_t cidx = (size_t)mg * HH + j;
        float cc = fg * g_c[cidx] + ig * gg;
        g_c[cidx] = cc;
        float h = og * tanhf(cc);
        Hist[((size_t)t * BB + mg) * HH + j] = h;
        nh16[cidx] = __float2half(h);
    }
}

// ---------------- output head ------------------------------------------------
__global__ void dense_out_kernel(const int* __restrict__ seq,
                                 const float* __restrict__ Wd,
                                 const float* __restrict__ bd,
                                 float* __restrict__ out)
{
    int b   = blockIdx.x;
    int tid = threadIdx.x;   // 128 threads
    const float* hrow = g_H2 + ((size_t)(seq[b] - 1) * BB + b) * HH;
    float s0 = 0.f, s1 = 0.f, s2 = 0.f;
    for (int j = tid; j < HH; j += 128) {
        float h = hrow[j];
        s0 += h * Wd[j * 3 + 0];
        s1 += h * Wd[j * 3 + 1];
        s2 += h * Wd[j * 3 + 2];
    }
    __shared__ float sm[3][128];
    sm[0][tid] = s0; sm[1][tid] = s1; sm[2][tid] = s2;
    __syncthreads();
    for (int s = 64; s > 0; s >>= 1) {
        if (tid < s) {
            sm[0][tid] += sm[0][tid + s];
            sm[1][tid] += sm[1][tid + s];
            sm[2][tid] += sm[2][tid + s];
        }
        __syncthreads();
    }
    if (tid == 0) {
        out[b * 3 + 0] = fmaxf(sm[0][0] + bd[0], 0.f);
        out[b * 3 + 1] = fmaxf(sm[1][0] + bd[1], 0.f);
        out[b * 3 + 2] = fmaxf(sm[2][0] + bd[2], 0.f);
    }
}

// ---------------- launch -----------------------------------------------------
extern "C" void kernel_launch(void* const* d_in, const int* in_sizes, int n_in,
                              void* d_out, int out_size)
{
    const float* chars = (const float*)d_in[0];
    const int*   seq   = (const int*)  d_in[1];
    const float* W1    = (const float*)d_in[2];
    const float* U1    = (const float*)d_in[3];
    const float* b1    = (const float*)d_in[4];
    const float* W2    = (const float*)d_in[5];
    const float* U2    = (const float*)d_in[6];
    const float* b2    = (const float*)d_in[7];
    const float* Wd    = (const float*)d_in[8];
    const float* bd    = (const float*)d_in[9];
    float*       out   = (float*)d_out;

    cudaFuncSetAttribute(lstm_step_mma, cudaFuncAttributeMaxDynamicSharedMemorySize,
                         SM_STEP_TOTAL);

    dim3 blk(256);
    dim3 gX(G4 / 128, MTOT / 128);   // 32 x 512
    dim3 gS(G4 / 128, BB / 64);      // 32 x 8 = 256 blocks

    // --- prep (inside the graph; cheap) ---
    reorder_W_kernel<<<(DIN * G4 + 255) / 256, 256>>>(W1, b1, DIN, 0);
    reorder_W_kernel<<<(HH  * G4 + 255) / 256, 256>>>(W2, b2, HH,  1);
    split_U_kernel<<<(G4 * HH + 255) / 256, 256>>>(U1, 0);
    split_U_kernel<<<(G4 * HH + 255) / 256, 256>>>(U2, 1);

    // --- layer 1 ---
    gemm_bias_kernel<DIN, true><<<gX, blk>>>(chars);
    zero_state_kernel<<<(BB * HH + 255) / 256, 256>>>();
    for (int t = 0; t < TT; t++)
        lstm_step_mma<<<gS, blk, SM_STEP_TOTAL>>>(t, 0);

    // --- layer 2 ---
    gemm_bias_kernel<HH, false><<<gX, blk>>>(nullptr);
    zero_state_kernel<<<(BB * HH + 255) / 256, 256>>>();
    for (int t = 0; t < TT; t++)
        lstm_step_mma<<<gS, blk, SM_STEP_TOTAL>>>(t, 1);

    // --- gather + dense + relu ---
    dense_out_kernel<<<BB, 128>>>(seq, Wd, bd, out);
}

// round 10
// speedup vs baseline: 1.1827x; 1.0113x over previous
#include <cuda_runtime.h>
#include <cuda_bf16.h>
#include <cuda_fp16.h>
#include <math.h>
#include <stdint.h>

#define BB   512
#define TT   128
#define DIN  256
#define HH   1024
#define G4   4096          // 4*HH
#define MTOT (TT*BB)       // 65536
#define NCH  16            // K chunks per step (1024/64)
#define CK   64            // k per chunk (64 fp16 = 128B rows)

// ---------------- scratch (device globals: no allocations allowed) ----------
__device__ float g_X [(size_t)TT * BB * G4];   // gate pre-activations (cols n=j*4+g)
__device__ float g_H1[(size_t)TT * BB * HH];   // layer-1 fp32 hidden history
__device__ float g_H2[(size_t)TT * BB * HH];   // layer-2 fp32 hidden history
__device__ float g_c [BB * HH];                // cell state (reused per layer)

__device__ float g_Wr1[(size_t)DIN * G4];      // W1 cols reordered n=j*4+g
__device__ float g_Wr2[(size_t)HH  * G4];
__device__ float g_br1[G4];
__device__ float g_br2[G4];

// U transposed+gate-interleaved+fp16-split: [layer][n=j*4+g][k]
__device__ __half g_Uhi[2][(size_t)G4 * HH];
__device__ __half g_Ulo[2][(size_t)G4 * HH];
// h ping-pong, single fp16: [parity][m*HH + j]
__device__ __half g_h16[2][(size_t)BB * HH];

// ---------------- helpers ----------------------------------------------------
__device__ __forceinline__ uint32_t smem_to_u32(const void* p) {
    uint32_t a;
    asm("{ .reg .u64 t; cvta.to.shared.u64 t, %1; cvt.u32.u64 %0, t; }"
        : "=r"(a) : "l"(p));
    return a;
}
#define SMEM_SWIZZLE_128B(b) ((b) ^ (((b) >> 3) & 0x70))

__device__ __forceinline__ void cp16(uint32_t dst, const void* src) {
    asm volatile("cp.async.cg.shared.global [%0], [%1], 16;" :: "r"(dst), "l"(src));
}
#define CP_COMMIT() asm volatile("cp.async.commit_group;" ::: "memory")
#define CP_WAIT(n)  asm volatile("cp.async.wait_group %0;" :: "n"(n) : "memory")

__device__ __forceinline__ void ldsm4(uint32_t* r, uint32_t addr) {
    asm volatile("ldmatrix.sync.aligned.m8n8.x4.shared.b16 {%0,%1,%2,%3}, [%4];"
        : "=r"(r[0]), "=r"(r[1]), "=r"(r[2]), "=r"(r[3]) : "r"(addr));
}
__device__ __forceinline__ void mma16816h(float* d, const uint32_t* a, const uint32_t* b) {
    asm volatile("mma.sync.aligned.m16n8k16.row.col.f32.f16.f16.f32 "
        "{%0,%1,%2,%3}, {%4,%5,%6,%7}, {%8,%9}, {%0,%1,%2,%3};"
        : "+f"(d[0]), "+f"(d[1]), "+f"(d[2]), "+f"(d[3])
        : "r"(a[0]), "r"(a[1]), "r"(a[2]), "r"(a[3]), "r"(b[0]), "r"(b[1]));
}

__device__ __forceinline__ float sigmoidf_(float x) { return 1.f / (1.f + expf(-x)); }

// ---------------- fp32x2 packed-FMA helpers (input GEMM path) ----------------
__device__ __forceinline__ unsigned long long dup2(float a) {
    unsigned long long r;
    asm("mov.b64 %0, {%1, %1};" : "=l"(r) : "r"(__float_as_uint(a)));
    return r;
}
__device__ __forceinline__ void ffma2(unsigned long long& d, unsigned long long a,
                                      unsigned long long b) {
    asm("fma.rn.f32x2 %0, %1, %2, %0;" : "+l"(d) : "l"(a), "l"(b));
}
__device__ __forceinline__ float lo2(unsigned long long v) { return __uint_as_float((unsigned)v); }
__device__ __forceinline__ float hi2(unsigned long long v) { return __uint_as_float((unsigned)(v >> 32)); }

// ============================================================================
// Prep kernels
// ============================================================================
__global__ void reorder_W_kernel(const float* __restrict__ W,
                                 const float* __restrict__ b,
                                 int KD, int sel)
{
    float* Wr = sel ? g_Wr2 : g_Wr1;
    float* br = sel ? g_br2 : g_br1;
    int i = blockIdx.x * blockDim.x + threadIdx.x;
    if (i < KD * G4) {
        int k = i >> 12, n = i & 4095;
        int j = n >> 2, g = n & 3;
        Wr[i] = W[(size_t)k * G4 + g * HH + j];
    }
    if (i < G4) {
        int j = i >> 2, g = i & 3;
        br[i] = b[g * HH + j];
    }
}

// Transpose + gate-interleave + fp16-split U: out[n=j*4+g][k] from U[k][g*HH+j]
__global__ void split_U_kernel(const float* __restrict__ U, int layer)
{
    int i = blockIdx.x * blockDim.x + threadIdx.x;   // i = n*HH + k
    if (i >= G4 * HH) return;
    int n = i >> 10, k = i & 1023;
    int j = n >> 2, g = n & 3;
    float v = U[(size_t)k * G4 + g * HH + j];
    __half hi = __float2half(v);
    __half lo = __float2half(v - __half2float(hi));
    g_Uhi[layer][i] = hi;
    g_Ulo[layer][i] = lo;
}

__global__ void zero_state_kernel()
{
    int i = blockIdx.x * blockDim.x + threadIdx.x;
    if (i < BB * HH) {
        g_c[i] = 0.f;
        g_h16[0][i] = __float2half(0.f);
    }
}

// ============================================================================
// Input-path GEMM (FFMA2, proven): g_X[m][n] = A[m][:] @ Wr[:, n] + br[n]
// ============================================================================
template<int KD, bool CHARS>
__global__ __launch_bounds__(256, 2)
void gemm_bias_kernel(const float* __restrict__ A)
{
    const float* __restrict__ W    = CHARS ? g_Wr1 : g_Wr2;
    const float* __restrict__ bias = CHARS ? g_br1 : g_br2;

    __shared__ __align__(16) float As[16][132];
    __shared__ __align__(16) float Bs[16][128];

    const int tid = threadIdx.x;
    const int tx  = tid & 15;
    const int ty  = tid >> 4;
    const int n0  = blockIdx.x * 128;
    const int m0  = blockIdx.y * 128;

    const float* Abase = CHARS ? A : g_H1;

    unsigned long long acc[8][4];
    #pragma unroll
    for (int i = 0; i < 8; i++)
        #pragma unroll
        for (int p = 0; p < 4; p++) acc[i][p] = 0ull;

    const int a_k = tid & 15;
    const int a_m = tid >> 4;
    const int b_c = tid & 127;
    const int b_k = tid >> 7;

    for (int kt = 0; kt < KD; kt += 16) {
        #pragma unroll
        for (int r = 0; r < 8; r++) {
            int m = m0 + a_m + 16 * r;
            size_t row = CHARS ? ((size_t)(m & 511) * TT + (m >> 9)) * KD
                               : (size_t)m * KD;
            As[a_k][a_m + 16 * r] = Abase[row + kt + a_k];
        }
        #pragma unroll
        for (int r = 0; r < 8; r++) {
            int k = b_k + 2 * r;
            Bs[k][b_c] = W[(size_t)(kt + k) * G4 + n0 + b_c];
        }
        __syncthreads();

        #pragma unroll
        for (int k = 0; k < 16; k++) {
            float4 a0 = *(const float4*)&As[k][ty * 4];
            float4 a1 = *(const float4*)&As[k][64 + ty * 4];
            unsigned long long bp[4];
            bp[0] = *(const unsigned long long*)&Bs[k][tx * 4];
            bp[1] = *(const unsigned long long*)&Bs[k][tx * 4 + 2];
            bp[2] = *(const unsigned long long*)&Bs[k][64 + tx * 4];
            bp[3] = *(const unsigned long long*)&Bs[k][64 + tx * 4 + 2];
            float av[8] = {a0.x, a0.y, a0.z, a0.w, a1.x, a1.y, a1.z, a1.w};
            #pragma unroll
            for (int i = 0; i < 8; i++) {
                unsigned long long ad = dup2(av[i]);
                #pragma unroll
                for (int p = 0; p < 4; p++) ffma2(acc[i][p], ad, bp[p]);
            }
        }
        __syncthreads();
    }

    #pragma unroll
    for (int i = 0; i < 8; i++) {
        int m = m0 + ((i < 4) ? (ty * 4 + i) : (64 + ty * 4 + i - 4));
        #pragma unroll
        for (int q = 0; q < 2; q++) {
            int n = n0 + q * 64 + tx * 4;
            float4 v;
            v.x = lo2(acc[i][q * 2])     + bias[n + 0];
            v.y = hi2(acc[i][q * 2])     + bias[n + 1];
            v.z = lo2(acc[i][q * 2 + 1]) + bias[n + 2];
            v.w = hi2(acc[i][q * 2 + 1]) + bias[n + 3];
            *(float4*)&g_X[(size_t)m * G4 + n] = v;
        }
    }
}

// ============================================================================
// Recurrent step: fp16 2-term mma.sync (z = h16@Uhi + h16@Ulo, fp32 acc).
// Block: M=128(batch) x N=128(=32j x 4gates), K=1024. grid (32,4)=128 blocks.
// 512 threads, 16 warps in 4(m) x 4(n), warp tile 32x32.
// 3-stage cp.async pipeline; stage = A 16KB + Bhi 16KB + Blo 16KB = 48KB.
// ============================================================================
#define STAGE_BYTES 49152
#define SM_STEP_TOTAL (3 * STAGE_BYTES)   // 147456

__device__ __forceinline__ void issue_chunk(
    uint32_t sb, int stage, int kt,
    const __half* h16, const __half* Uhi, const __half* Ulo,
    int m0, int nrow0, int tid)
{
    uint32_t base = sb + stage * STAGE_BYTES;
    uint32_t aA  = base;
    uint32_t bHi = base + 16384;
    uint32_t bLo = base + 32768;
    #pragma unroll
    for (int i = 0; i < 2; i++) {                 // A: 128 rows x 8 segs
        int idx = tid + 512 * i;
        int row = idx >> 3, cs = idx & 7;
        uint32_t off = SMEM_SWIZZLE_128B((uint32_t)(row * 128 + cs * 16));
        size_t src = (size_t)(m0 + row) * HH + kt + cs * 8;
        cp16(aA + off, h16 + src);
    }
    #pragma unroll
    for (int i = 0; i < 2; i++) {                 // B: 128 rows x 8 segs (hi+lo)
        int idx = tid + 512 * i;
        int row = idx >> 3, cs = idx & 7;
        uint32_t off = SMEM_SWIZZLE_128B((uint32_t)(row * 128 + cs * 16));
        size_t src = (size_t)(nrow0 + row) * HH + kt + cs * 8;
        cp16(bHi + off, Uhi + src);
        cp16(bLo + off, Ulo + src);
    }
    CP_COMMIT();
}

__global__ __launch_bounds__(512, 1)
void lstm_step_mma(int t, int layer)
{
    extern __shared__ __align__(128) char smem[];
    const uint32_t sb = smem_to_u32(smem);
    const int tid  = threadIdx.x;
    const int wid  = tid >> 5;
    const int lane = tid & 31;
    const int nrow0 = blockIdx.x * 128;   // n-rows of U for this block
    const int m0    = blockIdx.y * 128;
    const int par   = t & 1;

    const __half* h16 = g_h16[par];
    const __half* Uhi = g_Uhi[layer];
    const __half* Ulo = g_Ulo[layer];

    const int m_warp = (wid & 3) * 32;    // 4 m-tiles of 32
    const int n_warp = (wid >> 2) * 32;   // 4 n-tiles of 32

    float acc[2][4][4];
    #pragma unroll
    for (int mf = 0; mf < 2; mf++)
        #pragma unroll
        for (int nf = 0; nf < 4; nf++)
            #pragma unroll
            for (int d = 0; d < 4; d++) acc[mf][nf][d] = 0.f;

    const int rsel = lane & 15;
    const int csel = (lane >> 4) * 16;

    issue_chunk(sb, 0, 0,      h16, Uhi, Ulo, m0, nrow0, tid);
    issue_chunk(sb, 1, CK,     h16, Uhi, Ulo, m0, nrow0, tid);

    for (int c = 0; c < NCH; c++) {
        if (c + 1 < NCH) { CP_WAIT(1); } else { CP_WAIT(0); }
        __syncthreads();
        if (c + 2 < NCH)
            issue_chunk(sb, (c + 2) % 3, (c + 2) * CK, h16, Uhi, Ulo, m0, nrow0, tid);

        const uint32_t base = sb + (c % 3) * STAGE_BYTES;
        const uint32_t sA  = base;
        const uint32_t sBh = base + 16384;
        const uint32_t sBl = base + 32768;

        #pragma unroll
        for (int s = 0; s < 4; s++) {
            uint32_t aF[2][4], bH[4][2], bL[4][2];
            #pragma unroll
            for (int mf = 0; mf < 2; mf++) {
                uint32_t off = SMEM_SWIZZLE_128B(
                    (uint32_t)((m_warp + mf * 16 + rsel) * 128 + s * 32 + csel));
                ldsm4(aF[mf], sA + off);
            }
            #pragma unroll
            for (int nb = 0; nb < 2; nb++) {
                uint32_t off = SMEM_SWIZZLE_128B(
                    (uint32_t)((n_warp + nb * 16 + rsel) * 128 + s * 32 + csel));
                uint32_t r[4];
                ldsm4(r, sBh + off);
                bH[nb * 2][0] = r[0]; bH[nb * 2][1] = r[2];
                bH[nb * 2 + 1][0] = r[1]; bH[nb * 2 + 1][1] = r[3];
                ldsm4(r, sBl + off);
                bL[nb * 2][0] = r[0]; bL[nb * 2][1] = r[2];
                bL[nb * 2 + 1][0] = r[1]; bL[nb * 2 + 1][1] = r[3];
            }
            #pragma unroll
            for (int mf = 0; mf < 2; mf++)
                #pragma unroll
                for (int nf = 0; nf < 4; nf++) {
                    mma16816h(acc[mf][nf], aF[mf], bH[nf]);
                    mma16816h(acc[mf][nf], aF[mf], bL[nf]);
                }
        }
        __syncthreads();
    }

    // ---- epilogue: stage z via smem so each thread gets 4 gates of one j ----
    float* zs = (float*)smem;               // [128][132] fp32 = 67.6KB (reuses stages)
    #pragma unroll
    for (int mf = 0; mf < 2; mf++)
        #pragma unroll
        for (int nf = 0; nf < 4; nf++)
            #pragma unroll
            for (int d = 0; d < 4; d++) {
                int m = m_warp + mf * 16 + (lane >> 2) + (d >> 1) * 8;
                int n = n_warp + nf * 8 + (lane & 3) * 2 + (d & 1);
                zs[m * 132 + n] = acc[mf][nf][d];
            }
    __syncthreads();

    float* Hist = layer ? g_H2 : g_H1;
    __half* nh16 = g_h16[par ^ 1];
    const int j0 = blockIdx.x * 32;

    #pragma unroll
    for (int r = 0; r < 8; r++) {
        int e  = tid + 512 * r;             // < 4096 float4 slots
        int m  = e >> 5;
        int jl = e & 31;
        int mg = m0 + m;
        int j  = j0 + jl;
        float4 z = *(const float4*)&zs[m * 132 + jl * 4];
        const float* Xrow = g_X + ((size_t)t * BB + mg) * G4 + blockIdx.x * 128;
        float4 xz = *(const float4*)(Xrow + jl * 4);
        float zi = z.x + xz.x;
        float zf = z.y + xz.y;
        float zg = z.z + xz.z;
        float zo = z.w + xz.w;
        float ig = sigmoidf_(zi);
        float fg = sigmoidf_(zf);
        float gg = tanhf(zg);
        float og = sigmoidf_(zo);
        size_t cidx = (size_t)mg * HH + j;
        float cc = fg * g_c[cidx] + ig * gg;
        g_c[cidx] = cc;
        float h = og * tanhf(cc);
        Hist[((size_t)t * BB + mg) * HH + j] = h;
        nh16[cidx] = __float2half(h);
    }
}

// ---------------- output head ------------------------------------------------
__global__ void dense_out_kernel(const int* __restrict__ seq,
                                 const float* __restrict__ Wd,
                                 const float* __restrict__ bd,
                                 float* __restrict__ out)
{
    int b   = blockIdx.x;
    int tid = threadIdx.x;   // 128 threads
    const float* hrow = g_H2 + ((size_t)(seq[b] - 1) * BB + b) * HH;
    float s0 = 0.f, s1 = 0.f, s2 = 0.f;
    for (int j = tid; j < HH; j += 128) {
        float h = hrow[j];
        s0 += h * Wd[j * 3 + 0];
        s1 += h * Wd[j * 3 + 1];
        s2 += h * Wd[j * 3 + 2];
    }
    __shared__ float sm[3][128];
    sm[0][tid] = s0; sm[1][tid] = s1; sm[2][tid] = s2;
    __syncthreads();
    for (int s = 64; s > 0; s >>= 1) {
        if (tid < s) {
            sm[0][tid] += sm[0][tid + s];
            sm[1][tid] += sm[1][tid + s];
            sm[2][tid] += sm[2][tid + s];
        }
        __syncthreads();
    }
    if (tid == 0) {
        out[b * 3 + 0] = fmaxf(sm[0][0] + bd[0], 0.f);
        out[b * 3 + 1] = fmaxf(sm[1][0] + bd[1], 0.f);
        out[b * 3 + 2] = fmaxf(sm[2][0] + bd[2], 0.f);
    }
}

// ---------------- launch -----------------------------------------------------
extern "C" void kernel_launch(void* const* d_in, const int* in_sizes, int n_in,
                              void* d_out, int out_size)
{
    const float* chars = (const float*)d_in[0];
    const int*   seq   = (const int*)  d_in[1];
    const float* W1    = (const float*)d_in[2];
    const float* U1    = (const float*)d_in[3];
    const float* b1    = (const float*)d_in[4];
    const float* W2    = (const float*)d_in[5];
    const float* U2    = (const float*)d_in[6];
    const float* b2    = (const float*)d_in[7];
    const float* Wd    = (const float*)d_in[8];
    const float* bd    = (const float*)d_in[9];
    float*       out   = (float*)d_out;

    cudaFuncSetAttribute(lstm_step_mma, cudaFuncAttributeMaxDynamicSharedMemorySize,
                         SM_STEP_TOTAL);

    dim3 gX(G4 / 128, MTOT / 128);   // 32 x 512, 256 threads
    dim3 gS(G4 / 128, BB / 128);     // 32 x 4 = 128 blocks, 512 threads

    // --- prep (inside the graph; cheap) ---
    reorder_W_kernel<<<(DIN * G4 + 255) / 256, 256>>>(W1, b1, DIN, 0);
    reorder_W_kernel<<<(HH  * G4 + 255) / 256, 256>>>(W2, b2, HH,  1);
    split_U_kernel<<<(G4 * HH + 255) / 256, 256>>>(U1, 0);
    split_U_kernel<<<(G4 * HH + 255) / 256, 256>>>(U2, 1);

    // --- layer 1 ---
    gemm_bias_kernel<DIN, true><<<gX, 256>>>(chars);
    zero_state_kernel<<<(BB * HH + 255) / 256, 256>>>();
    for (int t = 0; t < TT; t++)
        lstm_step_mma<<<gS, 512, SM_STEP_TOTAL>>>(t, 0);

    // --- layer 2 ---
    gemm_bias_kernel<HH, false><<<gX, 256>>>(nullptr);
    zero_state_kernel<<<(BB * HH + 255) / 256, 256>>>();
    for (int t = 0; t < TT; t++)
        lstm_step_mma<<<gS, 512, SM_STEP_TOTAL>>>(t, 1);

    // --- gather + dense + relu ---
    dense_out_kernel<<<BB, 128>>>(seq, Wd, bd, out);
}

// round 11
// speedup vs baseline: 2.2908x; 1.9369x over previous
#include <cuda_runtime.h>
#include <cuda_bf16.h>
#include <cuda_fp16.h>
#include <math.h>
#include <stdint.h>

#define BB   512
#define TT   128
#define DIN  256
#define HH   1024
#define G4   4096          // 4*HH
#define MTOT (TT*BB)       // 65536
#define NCH  16            // K chunks (1024/64)
#define CK   64            // k per chunk (64 fp16 = 128B rows)

// ---------------- scratch (device globals: no allocations allowed) ----------
__device__ float g_X [(size_t)TT * BB * G4];   // gate pre-activations (cols n=j*4+g)
__device__ float g_H2[(size_t)TT * BB * HH];   // layer-2 fp32 hidden history (for head)
__device__ float g_c [BB * HH];                // cell state (reused per layer)

__device__ float g_Wr1[(size_t)DIN * G4];      // W1 cols reordered n=j*4+g (FFMA2 path)
__device__ float g_br1[G4];
__device__ float g_br2[G4];

// fp16 operands, transposed + gate-interleaved [n=j*4+g][k]:
//   slot 0 = U1, slot 1 = U2, slot 2 = W2
__device__ __half g_B16[3][(size_t)G4 * HH];
// h ping-pong fp16: [parity][m*HH + j]
__device__ __half g_h16[2][(size_t)BB * HH];
// layer-1 fp16 hidden history (A operand of the layer-2 input GEMM)
__device__ __half g_Hh16[(size_t)MTOT * HH];

// ---------------- helpers ----------------------------------------------------
__device__ __forceinline__ uint32_t smem_to_u32(const void* p) {
    uint32_t a;
    asm("{ .reg .u64 t; cvta.to.shared.u64 t, %1; cvt.u32.u64 %0, t; }"
        : "=r"(a) : "l"(p));
    return a;
}
#define SMEM_SWIZZLE_128B(b) ((b) ^ (((b) >> 3) & 0x70))

__device__ __forceinline__ void cp16(uint32_t dst, const void* src) {
    asm volatile("cp.async.cg.shared.global [%0], [%1], 16;" :: "r"(dst), "l"(src));
}
#define CP_COMMIT() asm volatile("cp.async.commit_group;" ::: "memory")
#define CP_WAIT(n)  asm volatile("cp.async.wait_group %0;" :: "n"(n) : "memory")

__device__ __forceinline__ void ldsm4(uint32_t* r, uint32_t addr) {
    asm volatile("ldmatrix.sync.aligned.m8n8.x4.shared.b16 {%0,%1,%2,%3}, [%4];"
        : "=r"(r[0]), "=r"(r[1]), "=r"(r[2]), "=r"(r[3]) : "r"(addr));
}
__device__ __forceinline__ void mma16816h(float* d, const uint32_t* a, const uint32_t* b) {
    asm volatile("mma.sync.aligned.m16n8k16.row.col.f32.f16.f16.f32 "
        "{%0,%1,%2,%3}, {%4,%5,%6,%7}, {%8,%9}, {%0,%1,%2,%3};"
        : "+f"(d[0]), "+f"(d[1]), "+f"(d[2]), "+f"(d[3])
        : "r"(a[0]), "r"(a[1]), "r"(a[2]), "r"(a[3]), "r"(b[0]), "r"(b[1]));
}

__device__ __forceinline__ float sigmoidf_(float x) { return 1.f / (1.f + expf(-x)); }

// ---------------- fp32x2 packed-FMA helpers (chars@W1 path) ------------------
__device__ __forceinline__ unsigned long long dup2(float a) {
    unsigned long long r;
    asm("mov.b64 %0, {%1, %1};" : "=l"(r) : "r"(__float_as_uint(a)));
    return r;
}
__device__ __forceinline__ void ffma2(unsigned long long& d, unsigned long long a,
                                      unsigned long long b) {
    asm("fma.rn.f32x2 %0, %1, %2, %0;" : "+l"(d) : "l"(a), "l"(b));
}
__device__ __forceinline__ float lo2(unsigned long long v) { return __uint_as_float((unsigned)v); }
__device__ __forceinline__ float hi2(unsigned long long v) { return __uint_as_float((unsigned)(v >> 32)); }

// ============================================================================
// Prep kernels
// ============================================================================
__global__ void reorder_W_kernel(const float* __restrict__ W,
                                 const float* __restrict__ b,
                                 int KD, int sel)
{
    int i = blockIdx.x * blockDim.x + threadIdx.x;
    if (sel == 0 && i < KD * G4) {
        int k = i >> 12, n = i & 4095;
        int j = n >> 2, g = n & 3;
        g_Wr1[i] = W[(size_t)k * G4 + g * HH + j];
    }
    if (i < G4) {
        int j = i >> 2, g = i & 3;
        (sel ? g_br2 : g_br1)[i] = b[g * HH + j];
    }
}

// Transpose + gate-interleave + fp16: out[slot][n=j*4+g][k] = fp16(M[k][g*HH+j])
__global__ void cvt_B_kernel(const float* __restrict__ M, int slot)
{
    int i = blockIdx.x * blockDim.x + threadIdx.x;   // i = n*HH + k
    if (i >= G4 * HH) return;
    int n = i >> 10, k = i & 1023;
    int j = n >> 2, g = n & 3;
    g_B16[slot][i] = __float2half(M[(size_t)k * G4 + g * HH + j]);
}

__global__ void zero_state_kernel()
{
    int i = blockIdx.x * blockDim.x + threadIdx.x;
    if (i < BB * HH) {
        g_c[i] = 0.f;
        g_h16[0][i] = __float2half(0.f);
    }
}

// ============================================================================
// chars@W1 GEMM (FFMA2, proven): g_X[m][n] = chars_row @ g_Wr1[:,n] + g_br1[n]
// ============================================================================
__global__ __launch_bounds__(256, 2)
void gemm1_kernel(const float* __restrict__ A)
{
    __shared__ __align__(16) float As[16][132];
    __shared__ __align__(16) float Bs[16][128];

    const int tid = threadIdx.x;
    const int tx  = tid & 15;
    const int ty  = tid >> 4;
    const int n0  = blockIdx.x * 128;
    const int m0  = blockIdx.y * 128;

    unsigned long long acc[8][4];
    #pragma unroll
    for (int i = 0; i < 8; i++)
        #pragma unroll
        for (int p = 0; p < 4; p++) acc[i][p] = 0ull;

    const int a_k = tid & 15;
    const int a_m = tid >> 4;
    const int b_c = tid & 127;
    const int b_k = tid >> 7;

    for (int kt = 0; kt < DIN; kt += 16) {
        #pragma unroll
        for (int r = 0; r < 8; r++) {
            int m = m0 + a_m + 16 * r;
            size_t row = ((size_t)(m & 511) * TT + (m >> 9)) * DIN;
            As[a_k][a_m + 16 * r] = A[row + kt + a_k];
        }
        #pragma unroll
        for (int r = 0; r < 8; r++) {
            int k = b_k + 2 * r;
            Bs[k][b_c] = g_Wr1[(size_t)(kt + k) * G4 + n0 + b_c];
        }
        __syncthreads();

        #pragma unroll
        for (int k = 0; k < 16; k++) {
            float4 a0 = *(const float4*)&As[k][ty * 4];
            float4 a1 = *(const float4*)&As[k][64 + ty * 4];
            unsigned long long bp[4];
            bp[0] = *(const unsigned long long*)&Bs[k][tx * 4];
            bp[1] = *(const unsigned long long*)&Bs[k][tx * 4 + 2];
            bp[2] = *(const unsigned long long*)&Bs[k][64 + tx * 4];
            bp[3] = *(const unsigned long long*)&Bs[k][64 + tx * 4 + 2];
            float av[8] = {a0.x, a0.y, a0.z, a0.w, a1.x, a1.y, a1.z, a1.w};
            #pragma unroll
            for (int i = 0; i < 8; i++) {
                unsigned long long ad = dup2(av[i]);
                #pragma unroll
                for (int p = 0; p < 4; p++) ffma2(acc[i][p], ad, bp[p]);
            }
        }
        __syncthreads();
    }

    #pragma unroll
    for (int i = 0; i < 8; i++) {
        int m = m0 + ((i < 4) ? (ty * 4 + i) : (64 + ty * 4 + i - 4));
        #pragma unroll
        for (int q = 0; q < 2; q++) {
            int n = n0 + q * 64 + tx * 4;
            float4 v;
            v.x = lo2(acc[i][q * 2])     + g_br1[n + 0];
            v.y = hi2(acc[i][q * 2])     + g_br1[n + 1];
            v.z = lo2(acc[i][q * 2 + 1]) + g_br1[n + 2];
            v.w = hi2(acc[i][q * 2 + 1]) + g_br1[n + 3];
            *(float4*)&g_X[(size_t)m * G4 + n] = v;
        }
    }
}

// ============================================================================
// Shared fp16 mma machinery: 128x128 tile, K=1024, 512 thr, 16 warps (4x4),
// warp tile 32x32, 1-term fp16, 3-stage cp.async (stage = A16KB + B16KB).
// ============================================================================
#define STAGE_BYTES 32768
#define SM_STEP_TOTAL (3 * STAGE_BYTES)   // 98304

__device__ __forceinline__ void issue_chunk(
    uint32_t sb, int stage, int kt,
    const __half* Aptr, const __half* Bptr,
    int m0, int nrow0, int tid)
{
    uint32_t base = sb + stage * STAGE_BYTES;
    uint32_t aA = base;
    uint32_t bB = base + 16384;
    #pragma unroll
    for (int i = 0; i < 2; i++) {                 // A: 128 rows x 8 x 16B
        int idx = tid + 512 * i;
        int row = idx >> 3, cs = idx & 7;
        uint32_t off = SMEM_SWIZZLE_128B((uint32_t)(row * 128 + cs * 16));
        cp16(aA + off, Aptr + (size_t)(m0 + row) * HH + kt + cs * 8);
    }
    #pragma unroll
    for (int i = 0; i < 2; i++) {                 // B: 128 rows x 8 x 16B
        int idx = tid + 512 * i;
        int row = idx >> 3, cs = idx & 7;
        uint32_t off = SMEM_SWIZZLE_128B((uint32_t)(row * 128 + cs * 16));
        cp16(bB + off, Bptr + (size_t)(nrow0 + row) * HH + kt + cs * 8);
    }
    CP_COMMIT();
}

// mainloop: accumulate acc[2][4][4] over K
__device__ __forceinline__ void mma_mainloop(
    uint32_t sb, const __half* Aptr, const __half* Bptr,
    int m0, int nrow0, int tid, int m_warp, int n_warp,
    int rsel, int csel, float acc[2][4][4])
{
    issue_chunk(sb, 0, 0,  Aptr, Bptr, m0, nrow0, tid);
    issue_chunk(sb, 1, CK, Aptr, Bptr, m0, nrow0, tid);

    for (int c = 0; c < NCH; c++) {
        if (c + 1 < NCH) { CP_WAIT(1); } else { CP_WAIT(0); }
        __syncthreads();
        if (c + 2 < NCH)
            issue_chunk(sb, (c + 2) % 3, (c + 2) * CK, Aptr, Bptr, m0, nrow0, tid);

        const uint32_t base = sb + (c % 3) * STAGE_BYTES;
        const uint32_t sA = base;
        const uint32_t sB = base + 16384;

        #pragma unroll
        for (int s = 0; s < 4; s++) {
            uint32_t aF[2][4], bF[4][2];
            #pragma unroll
            for (int mf = 0; mf < 2; mf++) {
                uint32_t off = SMEM_SWIZZLE_128B(
                    (uint32_t)((m_warp + mf * 16 + rsel) * 128 + s * 32 + csel));
                ldsm4(aF[mf], sA + off);
            }
            #pragma unroll
            for (int nb = 0; nb < 2; nb++) {
                uint32_t off = SMEM_SWIZZLE_128B(
                    (uint32_t)((n_warp + nb * 16 + rsel) * 128 + s * 32 + csel));
                uint32_t r[4];
                ldsm4(r, sB + off);
                bF[nb * 2][0] = r[0];     bF[nb * 2][1] = r[2];
                bF[nb * 2 + 1][0] = r[1]; bF[nb * 2 + 1][1] = r[3];
            }
            #pragma unroll
            for (int mf = 0; mf < 2; mf++)
                #pragma unroll
                for (int nf = 0; nf < 4; nf++)
                    mma16816h(acc[mf][nf], aF[mf], bF[nf]);
        }
        __syncthreads();
    }
}

// stage acc -> zs[128][132]
__device__ __forceinline__ void stage_z(float* zs, const float acc[2][4][4],
                                        int m_warp, int n_warp, int lane)
{
    #pragma unroll
    for (int mf = 0; mf < 2; mf++)
        #pragma unroll
        for (int nf = 0; nf < 4; nf++)
            #pragma unroll
            for (int d = 0; d < 4; d++) {
                int m = m_warp + mf * 16 + (lane >> 2) + (d >> 1) * 8;
                int n = n_warp + nf * 8 + (lane & 3) * 2 + (d & 1);
                zs[m * 132 + n] = acc[mf][nf][d];
            }
}

// ============================================================================
// Recurrent LSTM step (1-term fp16): grid (32, 4), 512 threads
// ============================================================================
__global__ __launch_bounds__(512, 1)
void lstm_step_mma(int t, int layer)
{
    extern __shared__ __align__(128) char smem[];
    const uint32_t sb = smem_to_u32(smem);
    const int tid  = threadIdx.x;
    const int wid  = tid >> 5;
    const int lane = tid & 31;
    const int nrow0 = blockIdx.x * 128;
    const int m0    = blockIdx.y * 128;
    const int par   = t & 1;

    const int m_warp = (wid & 3) * 32;
    const int n_warp = (wid >> 2) * 32;
    const int rsel = lane & 15;
    const int csel = (lane >> 4) * 16;

    float acc[2][4][4];
    #pragma unroll
    for (int mf = 0; mf < 2; mf++)
        #pragma unroll
        for (int nf = 0; nf < 4; nf++)
            #pragma unroll
            for (int d = 0; d < 4; d++) acc[mf][nf][d] = 0.f;

    mma_mainloop(sb, g_h16[par], g_B16[layer], m0, nrow0, tid,
                 m_warp, n_warp, rsel, csel, acc);

    float* zs = (float*)smem;
    stage_z(zs, acc, m_warp, n_warp, lane);
    __syncthreads();

    __half* nh16 = g_h16[par ^ 1];
    const int j0 = blockIdx.x * 32;

    #pragma unroll
    for (int r = 0; r < 8; r++) {
        int e  = tid + 512 * r;
        int m  = e >> 5;
        int jl = e & 31;
        int mg = m0 + m;
        int j  = j0 + jl;
        float4 z = *(const float4*)&zs[m * 132 + jl * 4];
        const float* Xrow = g_X + ((size_t)t * BB + mg) * G4 + blockIdx.x * 128;
        float4 xz = *(const float4*)(Xrow + jl * 4);
        float zi = z.x + xz.x;
        float zf = z.y + xz.y;
        float zg = z.z + xz.z;
        float zo = z.w + xz.w;
        float ig = sigmoidf_(zi);
        float fg = sigmoidf_(zf);
        float gg = tanhf(zg);
        float og = sigmoidf_(zo);
        size_t cidx = (size_t)mg * HH + j;
        float cc = fg * g_c[cidx] + ig * gg;
        g_c[cidx] = cc;
        float h = og * tanhf(cc);
        __half h16v = __float2half(h);
        nh16[cidx] = h16v;
        if (layer == 0)
            g_Hh16[((size_t)t * BB + mg) * HH + j] = h16v;   // for layer-2 GEMM
        else
            g_H2[((size_t)t * BB + mg) * HH + j] = h;        // for dense head
    }
}

// ============================================================================
// Layer-2 input GEMM via fp16 mma: g_X[m][n] = H1h16[m][:] @ W2_16[n][:] + br2
// grid (32, 512), 512 threads. Same tile machinery, no recurrence.
// ============================================================================
__global__ __launch_bounds__(512, 1)
void gemm2_mma_kernel()
{
    extern __shared__ __align__(128) char smem[];
    const uint32_t sb = smem_to_u32(smem);
    const int tid  = threadIdx.x;
    const int wid  = tid >> 5;
    const int lane = tid & 31;
    const int nrow0 = blockIdx.x * 128;
    const int m0    = blockIdx.y * 128;

    const int m_warp = (wid & 3) * 32;
    const int n_warp = (wid >> 2) * 32;
    const int rsel = lane & 15;
    const int csel = (lane >> 4) * 16;

    float acc[2][4][4];
    #pragma unroll
    for (int mf = 0; mf < 2; mf++)
        #pragma unroll
        for (int nf = 0; nf < 4; nf++)
            #pragma unroll
            for (int d = 0; d < 4; d++) acc[mf][nf][d] = 0.f;

    mma_mainloop(sb, g_Hh16, g_B16[2], m0, nrow0, tid,
                 m_warp, n_warp, rsel, csel, acc);

    float* zs = (float*)smem;
    stage_z(zs, acc, m_warp, n_warp, lane);
    __syncthreads();

    #pragma unroll
    for (int r = 0; r < 8; r++) {
        int e  = tid + 512 * r;
        int m  = e >> 5;
        int jl = e & 31;
        int mg = m0 + m;
        int n  = nrow0 + jl * 4;
        float4 z = *(const float4*)&zs[m * 132 + jl * 4];
        float4 v;
        v.x = z.x + g_br2[n + 0];
        v.y = z.y + g_br2[n + 1];
        v.z = z.z + g_br2[n + 2];
        v.w = z.w + g_br2[n + 3];
        *(float4*)&g_X[(size_t)mg * G4 + n] = v;
    }
}

// ---------------- output head ------------------------------------------------
__global__ void dense_out_kernel(const int* __restrict__ seq,
                                 const float* __restrict__ Wd,
                                 const float* __restrict__ bd,
                                 float* __restrict__ out)
{
    int b   = blockIdx.x;
    int tid = threadIdx.x;   // 128 threads
    const float* hrow = g_H2 + ((size_t)(seq[b] - 1) * BB + b) * HH;
    float s0 = 0.f, s1 = 0.f, s2 = 0.f;
    for (int j = tid; j < HH; j += 128) {
        float h = hrow[j];
        s0 += h * Wd[j * 3 + 0];
        s1 += h * Wd[j * 3 + 1];
        s2 += h * Wd[j * 3 + 2];
    }
    __shared__ float sm[3][128];
    sm[0][tid] = s0; sm[1][tid] = s1; sm[2][tid] = s2;
    __syncthreads();
    for (int s = 64; s > 0; s >>= 1) {
        if (tid < s) {
            sm[0][tid] += sm[0][tid + s];
            sm[1][tid] += sm[1][tid + s];
            sm[2][tid] += sm[2][tid + s];
        }
        __syncthreads();
    }
    if (tid == 0) {
        out[b * 3 + 0] = fmaxf(sm[0][0] + bd[0], 0.f);
        out[b * 3 + 1] = fmaxf(sm[1][0] + bd[1], 0.f);
        out[b * 3 + 2] = fmaxf(sm[2][0] + bd[2], 0.f);
    }
}

// ---------------- launch -----------------------------------------------------
extern "C" void kernel_launch(void* const* d_in, const int* in_sizes, int n_in,
                              void* d_out, int out_size)
{
    const float* chars = (const float*)d_in[0];
    const int*   seq   = (const int*)  d_in[1];
    const float* W1    = (const float*)d_in[2];
    const float* U1    = (const float*)d_in[3];
    const float* b1    = (const float*)d_in[4];
    const float* W2    = (const float*)d_in[5];
    const float* U2    = (const float*)d_in[6];
    const float* b2    = (const float*)d_in[7];
    const float* Wd    = (const float*)d_in[8];
    const float* bd    = (const float*)d_in[9];
    float*       out   = (float*)d_out;

    cudaFuncSetAttribute(lstm_step_mma, cudaFuncAttributeMaxDynamicSharedMemorySize,
                         SM_STEP_TOTAL);
    cudaFuncSetAttribute(gemm2_mma_kernel, cudaFuncAttributeMaxDynamicSharedMemorySize,
                         SM_STEP_TOTAL);

    dim3 g1(G4 / 128, MTOT / 128);   // 32 x 512 (FFMA2 chars@W1)
    dim3 gS(G4 / 128, BB / 128);     // 32 x 4 (recurrent step)
    dim3 g2(G4 / 128, MTOT / 128);   // 32 x 512 (mma H1@W2)

    // --- prep ---
    reorder_W_kernel<<<(DIN * G4 + 255) / 256, 256>>>(W1, b1, DIN, 0);
    reorder_W_kernel<<<(G4 + 255) / 256, 256>>>(W2, b2, HH, 1);   // bias2 only
    cvt_B_kernel<<<(G4 * HH + 255) / 256, 256>>>(U1, 0);
    cvt_B_kernel<<<(G4 * HH + 255) / 256, 256>>>(U2, 1);
    cvt_B_kernel<<<(G4 * HH + 255) / 256, 256>>>(W2, 2);

    // --- layer 1: X1 = chars@W1 + b1 (fp32), then 128 recurrent steps ---
    gemm1_kernel<<<g1, 256>>>(chars);
    zero_state_kernel<<<(BB * HH + 255) / 256, 256>>>();
    for (int t = 0; t < TT; t++)
        lstm_step_mma<<<gS, 512, SM_STEP_TOTAL>>>(t, 0);

    // --- layer 2: X2 = H1@W2 + b2 (fp16 mma), then 128 recurrent steps ---
    gemm2_mma_kernel<<<g2, 512, SM_STEP_TOTAL>>>();
    zero_state_kernel<<<(BB * HH + 255) / 256, 256>>>();
    for (int t = 0; t < TT; t++)
        lstm_step_mma<<<gS, 512, SM_STEP_TOTAL>>>(t, 1);

    // --- gather + dense + relu ---
    dense_out_kernel<<<BB, 128>>>(seq, Wd, bd, out);
}

// round 12
// speedup vs baseline: 2.9478x; 1.2868x over previous
#include <cuda_runtime.h>
#include <cuda_fp16.h>
#include <math.h>
#include <stdint.h>

#define BB   512
#define TT   128
#define DIN  256
#define HH   1024
#define G4   4096          // 4*HH
#define MTOT (TT*BB)       // 65536
#define CK   64            // k per chunk (64 fp16 = 128B rows)

// ---------------- scratch (device globals: no allocations allowed) ----------
__device__ float g_X [(size_t)TT * BB * G4];   // gate pre-activations (cols n=j*4+g)
__device__ float g_H2[(size_t)TT * BB * HH];   // layer-2 fp32 hidden history (head)
__device__ float g_c [BB * HH];                // cell state (reused per layer)
__device__ float g_br1[G4];
__device__ float g_br2[G4];

// fp16 B operands, transposed + gate-interleaved [n=j*4+g][k]:
//   slot 0 = U1, slot 1 = U2, slot 2 = W2   (k < HH)
__device__ __half g_B16[3][(size_t)G4 * HH];
__device__ __half g_W1h[(size_t)G4 * DIN];     // W1 [n][k], k < DIN
__device__ __half g_A1h[(size_t)MTOT * DIN];   // chars fp16, row m = t*BB+b
// h ping-pong fp16: [parity][m*HH + j]
__device__ __half g_h16[2][(size_t)BB * HH];
// layer-1 fp16 hidden history (A operand of layer-2 input GEMM)
__device__ __half g_Hh16[(size_t)MTOT * HH];

// ---------------- helpers ----------------------------------------------------
__device__ __forceinline__ uint32_t smem_to_u32(const void* p) {
    uint32_t a;
    asm("{ .reg .u64 t; cvta.to.shared.u64 t, %1; cvt.u32.u64 %0, t; }"
        : "=r"(a) : "l"(p));
    return a;
}
#define SMEM_SWIZZLE_128B(b) ((b) ^ (((b) >> 3) & 0x70))

__device__ __forceinline__ void cp16(uint32_t dst, const void* src) {
    asm volatile("cp.async.cg.shared.global [%0], [%1], 16;" :: "r"(dst), "l"(src));
}
#define CP_COMMIT() asm volatile("cp.async.commit_group;" ::: "memory")
#define CP_WAIT(n)  asm volatile("cp.async.wait_group %0;" :: "n"(n) : "memory")

__device__ __forceinline__ void ldsm4(uint32_t* r, uint32_t addr) {
    asm volatile("ldmatrix.sync.aligned.m8n8.x4.shared.b16 {%0,%1,%2,%3}, [%4];"
        : "=r"(r[0]), "=r"(r[1]), "=r"(r[2]), "=r"(r[3]) : "r"(addr));
}
__device__ __forceinline__ void mma16816h(float* d, const uint32_t* a, const uint32_t* b) {
    asm volatile("mma.sync.aligned.m16n8k16.row.col.f32.f16.f16.f32 "
        "{%0,%1,%2,%3}, {%4,%5,%6,%7}, {%8,%9}, {%0,%1,%2,%3};"
        : "+f"(d[0]), "+f"(d[1]), "+f"(d[2]), "+f"(d[3])
        : "r"(a[0]), "r"(a[1]), "r"(a[2]), "r"(a[3]), "r"(b[0]), "r"(b[1]));
}

// fast activations (abs err ~1e-6; negligible vs fp16 scheme error)
__device__ __forceinline__ float fsig(float x) {
    return __fdividef(1.f, 1.f + __expf(-x));
}
__device__ __forceinline__ float ftanh_(float x) {
    return 1.f - __fdividef(2.f, __expf(2.f * x) + 1.f);
}

// ============================================================================
// Prep kernels
// ============================================================================
__global__ void bias_kernel(const float* __restrict__ b1, const float* __restrict__ b2)
{
    int i = blockIdx.x * blockDim.x + threadIdx.x;
    if (i < G4) {
        int j = i >> 2, g = i & 3;
        g_br1[i] = b1[g * HH + j];
        g_br2[i] = b2[g * HH + j];
    }
}

// [k][G4] fp32 -> [n=j*4+g][k<HH] fp16
__global__ void cvt_B_kernel(const float* __restrict__ M, int slot)
{
    int i = blockIdx.x * blockDim.x + threadIdx.x;
    if (i >= G4 * HH) return;
    int n = i >> 10, k = i & 1023;
    int j = n >> 2, g = n & 3;
    g_B16[slot][i] = __float2half(M[(size_t)k * G4 + g * HH + j]);
}

// W1 [k<DIN][G4] -> [n][k] fp16
__global__ void cvt_W1_kernel(const float* __restrict__ W1)
{
    int i = blockIdx.x * blockDim.x + threadIdx.x;
    if (i >= G4 * DIN) return;
    int n = i >> 8, k = i & 255;
    int j = n >> 2, g = n & 3;
    g_W1h[i] = __float2half(W1[(size_t)k * G4 + g * HH + j]);
}

// chars [b][t][k] fp32 -> A1 [m=t*BB+b][k] fp16
__global__ void cvt_chars_kernel(const float* __restrict__ chars)
{
    int i = blockIdx.x * blockDim.x + threadIdx.x;
    if (i >= MTOT * DIN) return;
    int m = i >> 8, k = i & 255;
    int t = m >> 9, b = m & 511;
    g_A1h[i] = __float2half(chars[((size_t)b * TT + t) * DIN + k]);
}

__global__ void zero_state_kernel()
{
    int i = blockIdx.x * blockDim.x + threadIdx.x;
    if (i < BB * HH) {
        g_c[i] = 0.f;
        g_h16[0][i] = __float2half(0.f);
    }
}

// ============================================================================
// fp16 mma machinery (identical to R10): 128x128 tile, 512 thr, 16 warps (4x4),
// warp tile 32x32, 3-stage cp.async; stage = A 16KB + B 16KB = 32KB.
// Templated on KD (K dimension = row stride of A and B, multiple of 64).
// ============================================================================
#define STAGE_BYTES 32768
#define SM_STEP_TOTAL (3 * STAGE_BYTES)   // 98304

template<int KD>
__device__ __forceinline__ void issue_chunk(
    uint32_t sb, int stage, int kt,
    const __half* Aptr, const __half* Bptr,
    int m0, int nrow0, int tid)
{
    uint32_t base = sb + stage * STAGE_BYTES;
    uint32_t aA = base;
    uint32_t bB = base + 16384;
    #pragma unroll
    for (int i = 0; i < 2; i++) {                 // A: 128 rows x 8 x 16B
        int idx = tid + 512 * i;
        int row = idx >> 3, cs = idx & 7;
        uint32_t off = SMEM_SWIZZLE_128B((uint32_t)(row * 128 + cs * 16));
        cp16(aA + off, Aptr + (size_t)(m0 + row) * KD + kt + cs * 8);
    }
    #pragma unroll
    for (int i = 0; i < 2; i++) {                 // B: 128 rows x 8 x 16B
        int idx = tid + 512 * i;
        int row = idx >> 3, cs = idx & 7;
        uint32_t off = SMEM_SWIZZLE_128B((uint32_t)(row * 128 + cs * 16));
        cp16(bB + off, Bptr + (size_t)(nrow0 + row) * KD + kt + cs * 8);
    }
    CP_COMMIT();
}

template<int KD>
__device__ __forceinline__ void mma_mainloop(
    uint32_t sb, const __half* Aptr, const __half* Bptr,
    int m0, int nrow0, int tid, int m_warp, int n_warp,
    int rsel, int csel, float acc[2][4][4])
{
    const int NC = KD / CK;
    issue_chunk<KD>(sb, 0, 0,  Aptr, Bptr, m0, nrow0, tid);
    issue_chunk<KD>(sb, 1, CK, Aptr, Bptr, m0, nrow0, tid);

    for (int c = 0; c < NC; c++) {
        if (c + 1 < NC) { CP_WAIT(1); } else { CP_WAIT(0); }
        __syncthreads();
        if (c + 2 < NC)
            issue_chunk<KD>(sb, (c + 2) % 3, (c + 2) * CK, Aptr, Bptr, m0, nrow0, tid);

        const uint32_t base = sb + (c % 3) * STAGE_BYTES;
        const uint32_t sA = base;
        const uint32_t sB = base + 16384;

        #pragma unroll
        for (int s = 0; s < 4; s++) {
            uint32_t aF[2][4], bF[4][2];
            #pragma unroll
            for (int mf = 0; mf < 2; mf++) {
                uint32_t off = SMEM_SWIZZLE_128B(
                    (uint32_t)((m_warp + mf * 16 + rsel) * 128 + s * 32 + csel));
                ldsm4(aF[mf], sA + off);
            }
            #pragma unroll
            for (int nb = 0; nb < 2; nb++) {
                uint32_t off = SMEM_SWIZZLE_128B(
                    (uint32_t)((n_warp + nb * 16 + rsel) * 128 + s * 32 + csel));
                uint32_t r[4];
                ldsm4(r, sB + off);
                bF[nb * 2][0] = r[0];     bF[nb * 2][1] = r[2];
                bF[nb * 2 + 1][0] = r[1]; bF[nb * 2 + 1][1] = r[3];
            }
            #pragma unroll
            for (int mf = 0; mf < 2; mf++)
                #pragma unroll
                for (int nf = 0; nf < 4; nf++)
                    mma16816h(acc[mf][nf], aF[mf], bF[nf]);
        }
        __syncthreads();
    }
}

// stage acc -> zs[128][132]
__device__ __forceinline__ void stage_z(float* zs, const float acc[2][4][4],
                                        int m_warp, int n_warp, int lane)
{
    #pragma unroll
    for (int mf = 0; mf < 2; mf++)
        #pragma unroll
        for (int nf = 0; nf < 4; nf++)
            #pragma unroll
            for (int d = 0; d < 4; d++) {
                int m = m_warp + mf * 16 + (lane >> 2) + (d >> 1) * 8;
                int n = n_warp + nf * 8 + (lane & 3) * 2 + (d & 1);
                zs[m * 132 + n] = acc[mf][nf][d];
            }
}

// ============================================================================
// Recurrent LSTM step (1-term fp16): grid (32, 4), 512 threads
// ============================================================================
__global__ __launch_bounds__(512, 1)
void lstm_step_mma(int t, int layer)
{
    extern __shared__ __align__(128) char smem[];
    const uint32_t sb = smem_to_u32(smem);
    const int tid  = threadIdx.x;
    const int wid  = tid >> 5;
    const int lane = tid & 31;
    const int nrow0 = blockIdx.x * 128;
    const int m0    = blockIdx.y * 128;
    const int par   = t & 1;

    const int m_warp = (wid & 3) * 32;
    const int n_warp = (wid >> 2) * 32;
    const int rsel = lane & 15;
    const int csel = (lane >> 4) * 16;

    float acc[2][4][4];
    #pragma unroll
    for (int mf = 0; mf < 2; mf++)
        #pragma unroll
        for (int nf = 0; nf < 4; nf++)
            #pragma unroll
            for (int d = 0; d < 4; d++) acc[mf][nf][d] = 0.f;

    mma_mainloop<HH>(sb, g_h16[par], g_B16[layer], m0, nrow0, tid,
                     m_warp, n_warp, rsel, csel, acc);

    float* zs = (float*)smem;
    stage_z(zs, acc, m_warp, n_warp, lane);
    __syncthreads();

    __half* nh16 = g_h16[par ^ 1];
    const int j0 = blockIdx.x * 32;

    #pragma unroll
    for (int r = 0; r < 8; r++) {
        int e  = tid + 512 * r;
        int m  = e >> 5;
        int jl = e & 31;
        int mg = m0 + m;
        int j  = j0 + jl;
        float4 z = *(const float4*)&zs[m * 132 + jl * 4];
        const float* Xrow = g_X + ((size_t)t * BB + mg) * G4 + blockIdx.x * 128;
        float4 xz = *(const float4*)(Xrow + jl * 4);
        float ig = fsig(z.x + xz.x);
        float fg = fsig(z.y + xz.y);
        float gg = ftanh_(z.z + xz.z);
        float og = fsig(z.w + xz.w);
        size_t cidx = (size_t)mg * HH + j;
        float cc = fg * g_c[cidx] + ig * gg;
        g_c[cidx] = cc;
        float h = og * ftanh_(cc);
        __half h16v = __float2half(h);
        nh16[cidx] = h16v;
        if (layer == 0)
            g_Hh16[((size_t)t * BB + mg) * HH + j] = h16v;   // for layer-2 GEMM
        else
            g_H2[((size_t)t * BB + mg) * HH + j] = h;        // for dense head
    }
}

// ============================================================================
// Layer-1 input GEMM via fp16 mma (K=256): g_X = A1h @ W1h^T + br1
// grid (32, 512), 512 threads
// ============================================================================
__global__ __launch_bounds__(512, 1)
void gemm1_mma_kernel()
{
    extern __shared__ __align__(128) char smem[];
    const uint32_t sb = smem_to_u32(smem);
    const int tid  = threadIdx.x;
    const int wid  = tid >> 5;
    const int lane = tid & 31;
    const int nrow0 = blockIdx.x * 128;
    const int m0    = blockIdx.y * 128;

    const int m_warp = (wid & 3) * 32;
    const int n_warp = (wid >> 2) * 32;
    const int rsel = lane & 15;
    const int csel = (lane >> 4) * 16;

    float acc[2][4][4];
    #pragma unroll
    for (int mf = 0; mf < 2; mf++)
        #pragma unroll
        for (int nf = 0; nf < 4; nf++)
            #pragma unroll
            for (int d = 0; d < 4; d++) acc[mf][nf][d] = 0.f;

    mma_mainloop<DIN>(sb, g_A1h, g_W1h, m0, nrow0, tid,
                      m_warp, n_warp, rsel, csel, acc);

    float* zs = (float*)smem;
    stage_z(zs, acc, m_warp, n_warp, lane);
    __syncthreads();

    #pragma unroll
    for (int r = 0; r < 8; r++) {
        int e  = tid + 512 * r;
        int m  = e >> 5;
        int jl = e & 31;
        int mg = m0 + m;
        int n  = nrow0 + jl * 4;
        float4 z = *(const float4*)&zs[m * 132 + jl * 4];
        float4 v;
        v.x = z.x + g_br1[n + 0];
        v.y = z.y + g_br1[n + 1];
        v.z = z.z + g_br1[n + 2];
        v.w = z.w + g_br1[n + 3];
        *(float4*)&g_X[(size_t)mg * G4 + n] = v;
    }
}

// ============================================================================
// Layer-2 input GEMM via fp16 mma (K=1024): g_X = H1h16 @ W2h^T + br2
// grid (32, 512), 512 threads
// ============================================================================
__global__ __launch_bounds__(512, 1)
void gemm2_mma_kernel()
{
    extern __shared__ __align__(128) char smem[];
    const uint32_t sb = smem_to_u32(smem);
    const int tid  = threadIdx.x;
    const int wid  = tid >> 5;
    const int lane = tid & 31;
    const int nrow0 = blockIdx.x * 128;
    const int m0    = blockIdx.y * 128;

    const int m_warp = (wid & 3) * 32;
    const int n_warp = (wid >> 2) * 32;
    const int rsel = lane & 15;
    const int csel = (lane >> 4) * 16;

    float acc[2][4][4];
    #pragma unroll
    for (int mf = 0; mf < 2; mf++)
        #pragma unroll
        for (int nf = 0; nf < 4; nf++)
            #pragma unroll
            for (int d = 0; d < 4; d++) acc[mf][nf][d] = 0.f;

    mma_mainloop<HH>(sb, g_Hh16, g_B16[2], m0, nrow0, tid,
                     m_warp, n_warp, rsel, csel, acc);

    float* zs = (float*)smem;
    stage_z(zs, acc, m_warp, n_warp, lane);
    __syncthreads();

    #pragma unroll
    for (int r = 0; r < 8; r++) {
        int e  = tid + 512 * r;
        int m  = e >> 5;
        int jl = e & 31;
        int mg = m0 + m;
        int n  = nrow0 + jl * 4;
        float4 z = *(const float4*)&zs[m * 132 + jl * 4];
        float4 v;
        v.x = z.x + g_br2[n + 0];
        v.y = z.y + g_br2[n + 1];
        v.z = z.z + g_br2[n + 2];
        v.w = z.w + g_br2[n + 3];
        *(float4*)&g_X[(size_t)mg * G4 + n] = v;
    }
}

// ---------------- output head ------------------------------------------------
__global__ void dense_out_kernel(const int* __restrict__ seq,
                                 const float* __restrict__ Wd,
                                 const float* __restrict__ bd,
                                 float* __restrict__ out)
{
    int b   = blockIdx.x;
    int tid = threadIdx.x;   // 128 threads
    const float* hrow = g_H2 + ((size_t)(seq[b] - 1) * BB + b) * HH;
    float s0 = 0.f, s1 = 0.f, s2 = 0.f;
    for (int j = tid; j < HH; j += 128) {
        float h = hrow[j];
        s0 += h * Wd[j * 3 + 0];
        s1 += h * Wd[j * 3 + 1];
        s2 += h * Wd[j * 3 + 2];
    }
    __shared__ float sm[3][128];
    sm[0][tid] = s0; sm[1][tid] = s1; sm[2][tid] = s2;
    __syncthreads();
    for (int s = 64; s > 0; s >>= 1) {
        if (tid < s) {
            sm[0][tid] += sm[0][tid + s];
            sm[1][tid] += sm[1][tid + s];
            sm[2][tid] += sm[2][tid + s];
        }
        __syncthreads();
    }
    if (tid == 0) {
        out[b * 3 + 0] = fmaxf(sm[0][0] + bd[0], 0.f);
        out[b * 3 + 1] = fmaxf(sm[1][0] + bd[1], 0.f);
        out[b * 3 + 2] = fmaxf(sm[2][0] + bd[2], 0.f);
    }
}

// ---------------- launch -----------------------------------------------------
extern "C" void kernel_launch(void* const* d_in, const int* in_sizes, int n_in,
                              void* d_out, int out_size)
{
    const float* chars = (const float*)d_in[0];
    const int*   seq   = (const int*)  d_in[1];
    const float* W1    = (const float*)d_in[2];
    const float* U1    = (const float*)d_in[3];
    const float* b1    = (const float*)d_in[4];
    const float* W2    = (const float*)d_in[5];
    const float* U2    = (const float*)d_in[6];
    const float* b2    = (const float*)d_in[7];
    const float* Wd    = (const float*)d_in[8];
    const float* bd    = (const float*)d_in[9];
    float*       out   = (float*)d_out;

    cudaFuncSetAttribute(lstm_step_mma,  cudaFuncAttributeMaxDynamicSharedMemorySize, SM_STEP_TOTAL);
    cudaFuncSetAttribute(gemm1_mma_kernel, cudaFuncAttributeMaxDynamicSharedMemorySize, SM_STEP_TOTAL);
    cudaFuncSetAttribute(gemm2_mma_kernel, cudaFuncAttributeMaxDynamicSharedMemorySize, SM_STEP_TOTAL);

    dim3 gG(G4 / 128, MTOT / 128);   // 32 x 512 (input GEMMs)
    dim3 gS(G4 / 128, BB / 128);     // 32 x 4  (recurrent step)

    // --- prep ---
    bias_kernel<<<(G4 + 255) / 256, 256>>>(b1, b2);
    cvt_B_kernel<<<(G4 * HH + 255) / 256, 256>>>(U1, 0);
    cvt_B_kernel<<<(G4 * HH + 255) / 256, 256>>>(U2, 1);
    cvt_B_kernel<<<(G4 * HH + 255) / 256, 256>>>(W2, 2);
    cvt_W1_kernel<<<(G4 * DIN + 255) / 256, 256>>>(W1);
    cvt_chars_kernel<<<(MTOT * DIN + 255) / 256, 256>>>(chars);

    // --- layer 1: X1 = chars@W1 + b1 (fp16 mma), then 128 recurrent steps ---
    gemm1_mma_kernel<<<gG, 512, SM_STEP_TOTAL>>>();
    zero_state_kernel<<<(BB * HH + 255) / 256, 256>>>();
    for (int t = 0; t < TT; t++)
        lstm_step_mma<<<gS, 512, SM_STEP_TOTAL>>>(t, 0);

    // --- layer 2: X2 = H1@W2 + b2 (fp16 mma), then 128 recurrent steps ---
    gemm2_mma_kernel<<<gG, 512, SM_STEP_TOTAL>>>();
    zero_state_kernel<<<(BB * HH + 255) / 256, 256>>>();
    for (int t = 0; t < TT; t++)
        lstm_step_mma<<<gS, 512, SM_STEP_TOTAL>>>(t, 1);

    // --- gather + dense + relu ---
    dense_out_kernel<<<BB, 128>>>(seq, Wd, bd, out);
}